// round 7
// baseline (speedup 1.0000x reference)
#include <cuda_runtime.h>
#include <cstdint>

// ---------------------------------------------------------------------------
// VQ_16243566313849 round 7: legacy mma.sync m16n8k8 tf32, 3x-split fp32
// emulation for phase-2 (emb @ ze); phase-1 on packed FFMA2.
// R7 vs R6 (which had exactly ONE flipped argmin = near-tie precision):
//   (a) two-sweep mma ordering: correction terms (Ah*Bl + Al*Bh) accumulate
//       first at small magnitude, Ah*Bh last -> accumulator rounding ~2.4e-7.
//   (b) exact-fp32 rescore of the global top-2 candidates per column.
// ---------------------------------------------------------------------------

namespace {
constexpr int Bn  = 8;
constexpr int CIN = 768;
constexpr int Qd  = 128;
constexpr int Kn  = 4096;
constexpr int Nn  = 4096;

constexpr int TN      = 128;
constexpr int KTile   = 64;            // codebook rows per stage
constexpr int NTILES  = Kn / KTile;    // 64
constexpr int THREADS = 512;
constexpr int CK      = 32;            // phase-1 c chunk
constexpr int ZE_STR  = 132;           // phase-1 Wt/zt stride
constexpr int ZN_STR  = 136;           // ze [n][q] stride

// ---- smem float offsets ----
constexpr int P_ZE = 0;       // ze [128][136] = 17408 floats (aliases Wt/zt in ph1)
constexpr int ZSQ  = 17408;   // 128 floats
constexpr int IDX  = 17536;   // 128 ints
constexpr int P_A  = 17664;   // 2 x 16384-float A buffers (hi 8192 | lo 8192)
constexpr int SMEM_FLOATS = P_A + 32768;        // 50432
constexpr int SMEM_BYTES  = SMEM_FLOATS * 4;    // 201728 -> 1 block/SM
}

__device__ float d_emb_sq[Kn];
__device__ float d_eAH[(size_t)Kn * Qd];   // fragment-permuted emb hi (tf32 bits)
__device__ float d_eAL[(size_t)Kn * Qd];   // fragment-permuted emb lo

// ---------------- asm helpers ----------------------------------------------
__device__ __forceinline__ void fma2(unsigned long long& acc,
                                     unsigned long long a,
                                     unsigned long long b) {
    asm("fma.rn.f32x2 %0, %1, %2, %0;" : "+l"(acc) : "l"(a), "l"(b));
}
__device__ __forceinline__ unsigned long long dup2(float x) {
    unsigned long long r;
    unsigned int u = __float_as_uint(x);
    asm("mov.b64 %0, {%1, %1};" : "=l"(r) : "r"(u));
    return r;
}
__device__ __forceinline__ void unpack2(float& lo, float& hi,
                                        unsigned long long v) {
    unsigned int a, b2;
    asm("mov.b64 {%0, %1}, %2;" : "=r"(a), "=r"(b2) : "l"(v));
    lo = __uint_as_float(a); hi = __uint_as_float(b2);
}
__device__ __forceinline__ uint32_t f2tf32(float x) {
    uint32_t r;
    asm("cvt.rna.tf32.f32 %0, %1;" : "=r"(r) : "f"(x));
    return r;
}
__device__ __forceinline__ uint32_t smem_u32(const void* p) {
    uint32_t a;
    asm("{ .reg .u64 t; cvta.to.shared.u64 t, %1; cvt.u32.u64 %0, t; }"
        : "=r"(a) : "l"(p));
    return a;
}
__device__ __forceinline__ void cp_async16(uint32_t dst, const void* src) {
    asm volatile("cp.async.cg.shared.global [%0], [%1], 16;"
                 :: "r"(dst), "l"(src) : "memory");
}
__device__ __forceinline__ void cp_commit() {
    asm volatile("cp.async.commit_group;" ::: "memory");
}
__device__ __forceinline__ void cp_wait1() {
    asm volatile("cp.async.wait_group 1;" ::: "memory");
}
__device__ __forceinline__ void cp_wait0() {
    asm volatile("cp.async.wait_group 0;" ::: "memory");
}
__device__ __forceinline__ void mma_tf32(float c[4], const uint32_t a[4],
                                         uint32_t b0, uint32_t b1) {
    asm("mma.sync.aligned.m16n8k8.row.col.f32.tf32.tf32.f32 "
        "{%0,%1,%2,%3}, {%4,%5,%6,%7}, {%8,%9}, {%0,%1,%2,%3};"
        : "+f"(c[0]), "+f"(c[1]), "+f"(c[2]), "+f"(c[3])
        : "r"(a[0]), "r"(a[1]), "r"(a[2]), "r"(a[3]), "r"(b0), "r"(b1));
}

// ---------------- prologue kernels ------------------------------------------
__global__ void embsq_kernel(const float* __restrict__ emb) {
    int w = (blockIdx.x * blockDim.x + threadIdx.x) >> 5;
    int lane = threadIdx.x & 31;
    if (w >= Kn) return;
    const float* row = emb + (size_t)w * Qd;
    float s = 0.0f;
    #pragma unroll
    for (int j = 0; j < Qd / 32; ++j) { float v = row[lane + j * 32]; s = fmaf(v, v, s); }
    #pragma unroll
    for (int off = 16; off > 0; off >>= 1) s += __shfl_down_sync(0xffffffffu, s, off);
    if (lane == 0) d_emb_sq[w] = s;
}

// Fragment permutation: [ktile 64][ksub 4][s 16][lane 32][e 4]; for lane
// (g=lane>>2, t=lane&3): e0=(g, 8s+t) e1=(g+8, 8s+t) e2=(g, 8s+t+4) e3=(g+8, 8s+t+4)
__global__ void emb_frag_kernel(const float* __restrict__ emb) {
    int o = blockIdx.x * blockDim.x + threadIdx.x;
    if (o >= Kn * Qd) return;
    int kt = o >> 13;
    int r  = o & 8191;
    int ksub = r >> 11;
    int r2 = r & 2047;
    int s  = r2 >> 7;
    int r3 = r2 & 127;
    int ln = r3 >> 2;
    int e  = r3 & 3;
    int g = ln >> 2, t = ln & 3;
    int row = kt * 64 + ksub * 16 + g + 8 * (e & 1);
    int q   = 8 * s + t + 4 * (e >> 1);
    float v = emb[row * Qd + q];
    uint32_t h = f2tf32(v);
    d_eAH[o] = __uint_as_float(h);
    d_eAL[o] = v - __uint_as_float(h);
}

// ---------------- main kernel -----------------------------------------------
__global__ void __launch_bounds__(THREADS, 1)
vq_main_kernel(const float* __restrict__ z, const float* __restrict__ W,
               const float* __restrict__ emb, float* __restrict__ out) {
    extern __shared__ float fbase[];
    const uint32_t smemA_u = smem_u32(fbase) + (uint32_t)P_A * 4u;

    const int tid  = threadIdx.x;
    const int wid  = tid >> 5;
    const int lane = tid & 31;
    const int b    = blockIdx.y;
    const int n0b  = blockIdx.x * TN;

    // -------- prefetch A tiles 0 and 1 (P_A region free during phase 1) ----
    {
        #pragma unroll
        for (int tl = 0; tl < 2; ++tl) {
            const float* sH = d_eAH + (size_t)tl * 8192;
            const float* sL = d_eAL + (size_t)tl * 8192;
            const uint32_t dH = smemA_u + (uint32_t)tl * 65536u;
            #pragma unroll
            for (int k = 0; k < 4; ++k) {
                int c = tid + k * 512;
                cp_async16(dH + (uint32_t)c * 16u, sH + c * 4);
                cp_async16(dH + 32768u + (uint32_t)c * 16u, sL + c * 4);
            }
            cp_commit();
        }
    }

    // ================= Phase 1: ze = W @ z[b] tile (FFMA2) ==================
    {
        float* Wt = fbase + P_ZE;                 // [c][q] stride ZE_STR
        float* zt = fbase + P_ZE + CK * ZE_STR;   // [c][n] stride ZE_STR
        const int ty1 = tid >> 5;                 // q rows ty1*8..+7
        const int tx1 = tid & 31;                 // n cols tx1*4..+3

        unsigned long long acc1[4][4];
        #pragma unroll
        for (int i = 0; i < 4; ++i)
            #pragma unroll
            for (int j = 0; j < 4; ++j) acc1[i][j] = 0ull;

        for (int c0 = 0; c0 < CIN; c0 += CK) {
            for (int i = tid; i < CK * Qd; i += THREADS) {
                int c = i & (CK - 1);
                int q = i >> 5;
                Wt[c * ZE_STR + q] = W[q * CIN + c0 + c];
            }
            const float* zsrc = z + ((size_t)b * CIN + c0) * Nn + n0b;
            for (int i = tid; i < CK * TN; i += THREADS) {
                int r = i >> 7, nn = i & 127;
                zt[r * ZE_STR + nn] = zsrc[(size_t)r * Nn + nn];
            }
            __syncthreads();
            #pragma unroll 4
            for (int c = 0; c < CK; ++c) {
                const ulonglong2 ap0 =
                    *reinterpret_cast<const ulonglong2*>(Wt + c * ZE_STR + ty1 * 8);
                const ulonglong2 ap1 =
                    *reinterpret_cast<const ulonglong2*>(Wt + c * ZE_STR + ty1 * 8 + 4);
                const float4 bv =
                    *reinterpret_cast<const float4*>(zt + c * ZE_STR + tx1 * 4);
                const unsigned long long bd0 = dup2(bv.x), bd1 = dup2(bv.y);
                const unsigned long long bd2 = dup2(bv.z), bd3 = dup2(bv.w);
                fma2(acc1[0][0], ap0.x, bd0); fma2(acc1[0][1], ap0.x, bd1);
                fma2(acc1[0][2], ap0.x, bd2); fma2(acc1[0][3], ap0.x, bd3);
                fma2(acc1[1][0], ap0.y, bd0); fma2(acc1[1][1], ap0.y, bd1);
                fma2(acc1[1][2], ap0.y, bd2); fma2(acc1[1][3], ap0.y, bd3);
                fma2(acc1[2][0], ap1.x, bd0); fma2(acc1[2][1], ap1.x, bd1);
                fma2(acc1[2][2], ap1.x, bd2); fma2(acc1[2][3], ap1.x, bd3);
                fma2(acc1[3][0], ap1.y, bd0); fma2(acc1[3][1], ap1.y, bd1);
                fma2(acc1[3][2], ap1.y, bd2); fma2(acc1[3][3], ap1.y, bd3);
            }
            __syncthreads();   // Wt/zt dead after last iteration
        }
        // epilogue: write ze into [n][pos(q)] layout (Wt/zt region now dead)
        #pragma unroll
        for (int qp = 0; qp < 4; ++qp) {
            const int qb = ty1 * 8 + 2 * qp;
            #pragma unroll
            for (int nn = 0; nn < 4; ++nn) {
                float vlo, vhi; unpack2(vlo, vhi, acc1[qp][nn]);
                const int n = tx1 * 4 + nn;
                // pos(q) = (q & ~7) + 2*(q&3) + ((q>>2)&1)
                const int p0 = (qb & ~7) + 2 * (qb & 3) + ((qb >> 2) & 1);
                const int q1 = qb + 1;
                const int p1 = (q1 & ~7) + 2 * (q1 & 3) + ((q1 >> 2) & 1);
                fbase[P_ZE + n * ZN_STR + p0] = vlo;
                fbase[P_ZE + n * ZN_STR + p1] = vhi;
            }
        }
    }
    __syncthreads();

    // per-column ||ze||^2 (positions are a permutation of q)
    if (tid < 128) {
        const float* zr = fbase + P_ZE + tid * ZN_STR;
        float s = 0.0f;
        #pragma unroll 8
        for (int j = 0; j < Qd; ++j) { float v = zr[j]; s = fmaf(v, v, s); }
        fbase[ZSQ + tid] = s;
    }
    __syncthreads();

    // ================= Phase 2: mma.sync tf32 x3, two-sweep ================
    const int kw = wid & 3;          // k-subtile (16 rows) within 64-row tile
    const int nw = wid >> 2;         // n-group: cols nw*32 .. +31
    const int g  = lane >> 2;
    const int t  = lane & 3;

    float zsqr[8];
    #pragma unroll
    for (int nt = 0; nt < 4; ++nt)
        #pragma unroll
        for (int e = 0; e < 2; ++e)
            zsqr[nt * 2 + e] = fbase[ZSQ + nw * 32 + nt * 8 + 2 * t + e];

    float minv[8];
    int   mini[8];
    #pragma unroll
    for (int i = 0; i < 8; ++i) { minv[i] = 3.402823466e38f; mini[i] = 0; }

    const float2* zrow[4];
    #pragma unroll
    for (int nt = 0; nt < 4; ++nt)
        zrow[nt] = reinterpret_cast<const float2*>(
            fbase + P_ZE + (nw * 32 + nt * 8 + g) * ZN_STR);

    for (int tl = 0; tl < NTILES; ++tl) {
        if (tl < NTILES - 1) cp_wait1(); else cp_wait0();
        __syncthreads();

        const int bufo = (tl & 1) * 16384;
        const uint4* AH = reinterpret_cast<const uint4*>(
            fbase + P_A + bufo + kw * 2048) + lane;
        const uint4* AL = AH + 2048;   // +8192 floats = +2048 uint4

        float C[4][4];
        #pragma unroll
        for (int i = 0; i < 4; ++i)
            #pragma unroll
            for (int j = 0; j < 4; ++j) C[i][j] = 0.0f;

        // ---- sweep 1: small correction terms Ah*Bl + Al*Bh ----
        #pragma unroll 4
        for (int s = 0; s < 16; ++s) {
            const uint4 ahv = AH[s * 32];
            const uint4 alv = AL[s * 32];
            const uint32_t ah[4] = {ahv.x, ahv.y, ahv.z, ahv.w};
            const uint32_t al[4] = {alv.x, alv.y, alv.z, alv.w};
            #pragma unroll
            for (int nt = 0; nt < 4; ++nt) {
                const float2 braw = zrow[nt][s * 4 + t];
                const uint32_t bh0 = f2tf32(braw.x);
                const uint32_t bh1 = f2tf32(braw.y);
                const uint32_t bl0 =
                    __float_as_uint(braw.x - __uint_as_float(bh0));
                const uint32_t bl1 =
                    __float_as_uint(braw.y - __uint_as_float(bh1));
                mma_tf32(C[nt], ah, bl0, bl1);
                mma_tf32(C[nt], al, bh0, bh1);
            }
        }
        // ---- sweep 2: dominant Ah*Bh terms (last -> minimal rounding) ----
        #pragma unroll 4
        for (int s = 0; s < 16; ++s) {
            const uint4 ahv = AH[s * 32];
            const uint32_t ah[4] = {ahv.x, ahv.y, ahv.z, ahv.w};
            #pragma unroll
            for (int nt = 0; nt < 4; ++nt) {
                const float2 braw = zrow[nt][s * 4 + t];
                const uint32_t bh0 = f2tf32(braw.x);
                const uint32_t bh1 = f2tf32(braw.y);
                mma_tf32(C[nt], ah, bh0, bh1);
            }
        }

        // epilogue: d2 = zsq - 2*cross + emb_sq, thread-local argmin
        const int k0 = tl * KTile + kw * 16;
        const float e0 = __ldg(&d_emb_sq[k0 + g]);
        const float e8 = __ldg(&d_emb_sq[k0 + g + 8]);
        #pragma unroll
        for (int nt = 0; nt < 4; ++nt)
            #pragma unroll
            for (int e = 0; e < 2; ++e) {
                const int i = nt * 2 + e;
                float d2 = fmaf(-2.0f, C[nt][e], zsqr[i]) + e0;
                if (d2 < minv[i]) { minv[i] = d2; mini[i] = k0 + g; }
                d2 = fmaf(-2.0f, C[nt][2 + e], zsqr[i]) + e8;
                if (d2 < minv[i]) { minv[i] = d2; mini[i] = k0 + g + 8; }
            }

        __syncthreads();   // all warps done with buffer (tl&1) before restage
        if (tl + 2 < NTILES) {
            const int nxt = tl + 2;
            const float* sH = d_eAH + (size_t)nxt * 8192;
            const float* sL = d_eAL + (size_t)nxt * 8192;
            const uint32_t dH = smemA_u + (uint32_t)(tl & 1) * 65536u;
            #pragma unroll
            for (int k = 0; k < 4; ++k) {
                int c = tid + k * 512;
                cp_async16(dH + (uint32_t)c * 16u, sH + c * 4);
                cp_async16(dH + 32768u + (uint32_t)c * 16u, sL + c * 4);
            }
            cp_commit();
        }
    }
    __syncthreads();

    // ====== cross-thread top-2 reduce + exact fp32 rescore per column ======
    {
        float* rv = fbase + P_A;                         // [32 slots][128 n]
        int*   ri = reinterpret_cast<int*>(fbase + P_A + 4096);
        const int slot = kw * 8 + g;
        #pragma unroll
        for (int nt = 0; nt < 4; ++nt)
            #pragma unroll
            for (int e = 0; e < 2; ++e) {
                const int n = nw * 32 + nt * 8 + 2 * t + e;
                rv[slot * 128 + n] = minv[nt * 2 + e];
                ri[slot * 128 + n] = mini[nt * 2 + e];
            }
        __syncthreads();
        if (tid < 128) {
            float v1 = 3.402823466e38f, v2 = 3.402823466e38f;
            int   i1 = 0, i2 = 0;
            #pragma unroll
            for (int sl = 0; sl < 32; ++sl) {
                const float v  = rv[sl * 128 + tid];
                const int   ix = ri[sl * 128 + tid];
                if (v < v1 || (v == v1 && ix < i1)) {
                    v2 = v1; i2 = i1; v1 = v; i1 = ix;
                } else if (v < v2 || (v == v2 && ix < i2)) {
                    v2 = v; i2 = ix;
                }
            }
            // exact fp32 rescore of both candidates (sequential over q)
            const float* zr = fbase + P_ZE + tid * ZN_STR;
            const float* e1 = emb + (size_t)i1 * Qd;
            const float* e2 = emb + (size_t)i2 * Qd;
            float dot1 = 0.0f, dot2 = 0.0f;
            #pragma unroll 8
            for (int q = 0; q < Qd; ++q) {
                const int p = (q & ~7) + 2 * (q & 3) + ((q >> 2) & 1);
                const float zv = zr[p];
                dot1 = fmaf(e1[q], zv, dot1);
                dot2 = fmaf(e2[q], zv, dot2);
            }
            const float zsqn = fbase[ZSQ + tid];
            const float da = fmaf(-2.0f, dot1, zsqn) + __ldg(&d_emb_sq[i1]);
            const float db = fmaf(-2.0f, dot2, zsqn) + __ldg(&d_emb_sq[i2]);
            int best;
            if (i1 < i2) best = (db < da) ? i2 : i1;   // tie -> lower index
            else         best = (da < db) ? i1 : i2;
            reinterpret_cast<int*>(fbase + IDX)[tid] = best;
        }
        __syncthreads();
    }

    // ============== gather: out[b][q][n] = emb[idx[n]][q] ==================
    {
        const int* idx_s = reinterpret_cast<const int*>(fbase + IDX);
        float* gbuf = fbase + P_A;   // 128 x 129
        for (int i = tid; i < Qd * TN; i += THREADS) {
            int n = i >> 7, q = i & 127;
            gbuf[n * 129 + q] = emb[(size_t)idx_s[n] * Qd + q];
        }
        __syncthreads();
        for (int i = tid; i < Qd * TN; i += THREADS) {
            int q = i >> 7, n = i & 127;
            out[((size_t)b * Qd + q) * Nn + n0b + n] = gbuf[n * 129 + q];
        }
    }
}

// ---------------------------------------------------------------------------
extern "C" void kernel_launch(void* const* d_in, const int* in_sizes, int n_in,
                              void* d_out, int out_size) {
    const float* z = nullptr; const float* W = nullptr; const float* emb = nullptr;
    for (int i = 0; i < n_in; ++i) {
        if (in_sizes[i] == Bn * CIN * Nn)   z   = (const float*)d_in[i];
        else if (in_sizes[i] == Qd * CIN)   W   = (const float*)d_in[i];
        else if (in_sizes[i] == Kn * Qd)    emb = (const float*)d_in[i];
    }
    float* out = (float*)d_out;

    cudaFuncSetAttribute(vq_main_kernel,
                         cudaFuncAttributeMaxDynamicSharedMemorySize, SMEM_BYTES);

    embsq_kernel<<<Kn * 32 / 256, 256>>>(emb);
    emb_frag_kernel<<<(Kn * Qd + 255) / 256, 256>>>(emb);
    dim3 grid(Nn / TN, Bn);
    vq_main_kernel<<<grid, THREADS, SMEM_BYTES>>>(z, W, emb, out);
}

// round 8
// speedup vs baseline: 1.5853x; 1.5853x over previous
#include <cuda_runtime.h>
#include <cuda_bf16.h>
#include <cstdint>

// ---------------------------------------------------------------------------
// VQ_16243566313849 round 8: phase-2 on mma.sync m16n8k16 BF16 with 3-term
// split-bf16 fp32 emulation (hh + hl + lh; corrections in a separate
// accumulator). ze pre-split to packed bf16 hi/lo in smem once; emb hi/lo
// prepacked in gmem fragment order. Top-2 exact-fp32 rescore (proven in R7)
// absorbs the ~2e-5 emulation noise. Phase-1 stays FFMA2.
// ---------------------------------------------------------------------------

namespace {
constexpr int Bn  = 8;
constexpr int CIN = 768;
constexpr int Qd  = 128;
constexpr int Kn  = 4096;
constexpr int Nn  = 4096;

constexpr int TN      = 128;
constexpr int KTile   = 64;            // codebook rows per stage
constexpr int NTILES  = Kn / KTile;    // 64
constexpr int THREADS = 512;
constexpr int CK      = 32;            // phase-1 c chunk
constexpr int ZE_STR  = 132;           // phase-1 Wt/zt stride
constexpr int ZN_STR  = 136;           // ze fp32 [n][q] stride
constexpr int ZB_STR  = 72;            // packed-bf16 ze row stride (words)

// ---- smem float(=word) offsets ----
constexpr int P_ZE = 0;       // ze fp32 [128][136] = 17408 (aliases Wt/zt ph1;
                              //   reused as gather buffer at the very end)
constexpr int ZSQ  = 17408;   // 128
constexpr int IDX  = 17536;   // 128
constexpr int ZBH  = 17664;   // 128 x 72 words, packed bf16x2 ze hi
constexpr int ZBL  = ZBH + 128 * ZB_STR;        // 26880
constexpr int P_A  = ZBL + 128 * ZB_STR;        // 36096: 2 bufs x 8192 words
constexpr int SMEM_FLOATS = P_A + 16384;        // 52480
constexpr int SMEM_BYTES  = SMEM_FLOATS * 4;    // 209920 -> 1 block/SM
}

__device__ float    d_emb_sq[Kn];
__device__ uint32_t d_ebAH[(size_t)Kn * 64];   // frag-packed emb hi (bf16x2)
__device__ uint32_t d_ebAL[(size_t)Kn * 64];   // frag-packed emb lo (bf16x2)

// ---------------- asm helpers ----------------------------------------------
__device__ __forceinline__ void fma2(unsigned long long& acc,
                                     unsigned long long a,
                                     unsigned long long b) {
    asm("fma.rn.f32x2 %0, %1, %2, %0;" : "+l"(acc) : "l"(a), "l"(b));
}
__device__ __forceinline__ unsigned long long dup2(float x) {
    unsigned long long r;
    unsigned int u = __float_as_uint(x);
    asm("mov.b64 %0, {%1, %1};" : "=l"(r) : "r"(u));
    return r;
}
__device__ __forceinline__ void unpack2(float& lo, float& hi,
                                        unsigned long long v) {
    unsigned int a, b2;
    asm("mov.b64 {%0, %1}, %2;" : "=r"(a), "=r"(b2) : "l"(v));
    lo = __uint_as_float(a); hi = __uint_as_float(b2);
}
__device__ __forceinline__ uint32_t smem_u32(const void* p) {
    uint32_t a;
    asm("{ .reg .u64 t; cvta.to.shared.u64 t, %1; cvt.u32.u64 %0, t; }"
        : "=r"(a) : "l"(p));
    return a;
}
__device__ __forceinline__ void cp_async16(uint32_t dst, const void* src) {
    asm volatile("cp.async.cg.shared.global [%0], [%1], 16;"
                 :: "r"(dst), "l"(src) : "memory");
}
__device__ __forceinline__ void cp_commit() {
    asm volatile("cp.async.commit_group;" ::: "memory");
}
__device__ __forceinline__ void cp_wait1() {
    asm volatile("cp.async.wait_group 1;" ::: "memory");
}
__device__ __forceinline__ void cp_wait0() {
    asm volatile("cp.async.wait_group 0;" ::: "memory");
}
__device__ __forceinline__ void mma_bf16(float c[4], const uint32_t a[4],
                                         uint32_t b0, uint32_t b1) {
    asm("mma.sync.aligned.m16n8k16.row.col.f32.bf16.bf16.f32 "
        "{%0,%1,%2,%3}, {%4,%5,%6,%7}, {%8,%9}, {%0,%1,%2,%3};"
        : "+f"(c[0]), "+f"(c[1]), "+f"(c[2]), "+f"(c[3])
        : "r"(a[0]), "r"(a[1]), "r"(a[2]), "r"(a[3]), "r"(b0), "r"(b1));
}

// ---------------- prologue kernels ------------------------------------------
__global__ void embsq_kernel(const float* __restrict__ emb) {
    int w = (blockIdx.x * blockDim.x + threadIdx.x) >> 5;
    int lane = threadIdx.x & 31;
    if (w >= Kn) return;
    const float* row = emb + (size_t)w * Qd;
    float s = 0.0f;
    #pragma unroll
    for (int j = 0; j < Qd / 32; ++j) { float v = row[lane + j * 32]; s = fmaf(v, v, s); }
    #pragma unroll
    for (int off = 16; off > 0; off >>= 1) s += __shfl_down_sync(0xffffffffu, s, off);
    if (lane == 0) d_emb_sq[w] = s;
}

// Pack emb into m16n8k16 A-fragment order, bf16 hi/lo, one uint32 = 2 bf16.
// Layout: [kt 64][ksub 4][s 8][lane 32][r 4]; lane=(g,t): reg r covers
// A row = base + g + 8*(r&1), q pair = s*16 + 2t + 8*(r>>1) .. +1.
__global__ void emb_pack_kernel(const float* __restrict__ emb) {
    int o = blockIdx.x * blockDim.x + threadIdx.x;
    if (o >= Kn * 64) return;
    int kt = o >> 12, r1 = o & 4095;
    int ksub = r1 >> 10, r2 = r1 & 1023;
    int s = r2 >> 7, r3 = r2 & 127;
    int lane = r3 >> 2, r = r3 & 3;
    int g = lane >> 2, t = lane & 3;
    int row = kt * 64 + ksub * 16 + g + 8 * (r & 1);
    int q0  = s * 16 + 2 * t + 8 * (r >> 1);
    float v0 = emb[row * Qd + q0];
    float v1 = emb[row * Qd + q0 + 1];
    __nv_bfloat16 h0 = __float2bfloat16(v0), h1 = __float2bfloat16(v1);
    __nv_bfloat16 l0 = __float2bfloat16(v0 - __bfloat162float(h0));
    __nv_bfloat16 l1 = __float2bfloat16(v1 - __bfloat162float(h1));
    d_ebAH[o] = (uint32_t)__bfloat16_as_ushort(h0) |
                ((uint32_t)__bfloat16_as_ushort(h1) << 16);
    d_ebAL[o] = (uint32_t)__bfloat16_as_ushort(l0) |
                ((uint32_t)__bfloat16_as_ushort(l1) << 16);
}

// ---------------- main kernel -----------------------------------------------
__global__ void __launch_bounds__(THREADS, 1)
vq_main_kernel(const float* __restrict__ z, const float* __restrict__ W,
               const float* __restrict__ emb, float* __restrict__ out) {
    extern __shared__ float fbase[];
    const uint32_t smemA_u = smem_u32(fbase) + (uint32_t)P_A * 4u;

    const int tid  = threadIdx.x;
    const int wid  = tid >> 5;
    const int lane = tid & 31;
    const int b    = blockIdx.y;
    const int n0b  = blockIdx.x * TN;

    // -------- prefetch A tiles 0 and 1 (P_A free during phase 1) ----------
    {
        #pragma unroll
        for (int tl = 0; tl < 2; ++tl) {
            const uint32_t* sH = d_ebAH + (size_t)tl * 4096;
            const uint32_t* sL = d_ebAL + (size_t)tl * 4096;
            const uint32_t dst = smemA_u + (uint32_t)tl * 32768u;
            #pragma unroll
            for (int c0 = 0; c0 < 1024; c0 += 512) {
                int c = tid + c0;
                cp_async16(dst + (uint32_t)c * 16u, sH + c * 4);
                cp_async16(dst + 16384u + (uint32_t)c * 16u, sL + c * 4);
            }
            cp_commit();
        }
    }

    // ================= Phase 1: ze = W @ z[b] tile (FFMA2) ==================
    {
        float* Wt = fbase + P_ZE;                 // [c][q] stride ZE_STR
        float* zt = fbase + P_ZE + CK * ZE_STR;   // [c][n] stride ZE_STR
        const int ty1 = tid >> 5;                 // q rows ty1*8..+7
        const int tx1 = tid & 31;                 // n cols tx1*4..+3

        unsigned long long acc1[4][4];
        #pragma unroll
        for (int i = 0; i < 4; ++i)
            #pragma unroll
            for (int j = 0; j < 4; ++j) acc1[i][j] = 0ull;

        for (int c0 = 0; c0 < CIN; c0 += CK) {
            for (int i = tid; i < CK * Qd; i += THREADS) {
                int c = i & (CK - 1);
                int q = i >> 5;
                Wt[c * ZE_STR + q] = W[q * CIN + c0 + c];
            }
            const float* zsrc = z + ((size_t)b * CIN + c0) * Nn + n0b;
            for (int i = tid; i < CK * TN; i += THREADS) {
                int r = i >> 7, nn = i & 127;
                zt[r * ZE_STR + nn] = zsrc[(size_t)r * Nn + nn];
            }
            __syncthreads();
            #pragma unroll 4
            for (int c = 0; c < CK; ++c) {
                const ulonglong2 ap0 =
                    *reinterpret_cast<const ulonglong2*>(Wt + c * ZE_STR + ty1 * 8);
                const ulonglong2 ap1 =
                    *reinterpret_cast<const ulonglong2*>(Wt + c * ZE_STR + ty1 * 8 + 4);
                const float4 bv =
                    *reinterpret_cast<const float4*>(zt + c * ZE_STR + tx1 * 4);
                const unsigned long long bd0 = dup2(bv.x), bd1 = dup2(bv.y);
                const unsigned long long bd2 = dup2(bv.z), bd3 = dup2(bv.w);
                fma2(acc1[0][0], ap0.x, bd0); fma2(acc1[0][1], ap0.x, bd1);
                fma2(acc1[0][2], ap0.x, bd2); fma2(acc1[0][3], ap0.x, bd3);
                fma2(acc1[1][0], ap0.y, bd0); fma2(acc1[1][1], ap0.y, bd1);
                fma2(acc1[1][2], ap0.y, bd2); fma2(acc1[1][3], ap0.y, bd3);
                fma2(acc1[2][0], ap1.x, bd0); fma2(acc1[2][1], ap1.x, bd1);
                fma2(acc1[2][2], ap1.x, bd2); fma2(acc1[2][3], ap1.x, bd3);
                fma2(acc1[3][0], ap1.y, bd0); fma2(acc1[3][1], ap1.y, bd1);
                fma2(acc1[3][2], ap1.y, bd2); fma2(acc1[3][3], ap1.y, bd3);
            }
            __syncthreads();   // Wt/zt dead after last iteration
        }
        // epilogue: fp32 ze into [n][pos(q)] AND packed bf16 hi/lo split
        ushort* zbh16 = reinterpret_cast<ushort*>(fbase + ZBH);
        ushort* zbl16 = reinterpret_cast<ushort*>(fbase + ZBL);
        #pragma unroll
        for (int qp = 0; qp < 4; ++qp) {
            const int qb = ty1 * 8 + 2 * qp;
            #pragma unroll
            for (int nn = 0; nn < 4; ++nn) {
                float vlo, vhi; unpack2(vlo, vhi, acc1[qp][nn]);
                const int n = tx1 * 4 + nn;
                #pragma unroll
                for (int h = 0; h < 2; ++h) {
                    const int q = qb + h;
                    const float v = h ? vhi : vlo;
                    // fp32 store at pos(q) = (q&~7) + 2*(q&3) + ((q>>2)&1)
                    const int p = (q & ~7) + 2 * (q & 3) + ((q >> 2) & 1);
                    fbase[P_ZE + n * ZN_STR + p] = v;
                    // bf16 split store: word = (q>>4)*8 + 2*((q&7)>>1) + ((q>>3)&1)
                    const int w2 = ((q >> 4) << 3) + (((q & 7) >> 1) << 1) +
                                   ((q >> 3) & 1);
                    const int ix = n * (2 * ZB_STR) + w2 * 2 + (q & 1);
                    __nv_bfloat16 hb = __float2bfloat16(v);
                    __nv_bfloat16 lb =
                        __float2bfloat16(v - __bfloat162float(hb));
                    zbh16[ix] = __bfloat16_as_ushort(hb);
                    zbl16[ix] = __bfloat16_as_ushort(lb);
                }
            }
        }
    }
    __syncthreads();

    // per-column ||ze||^2
    if (tid < 128) {
        const float* zr = fbase + P_ZE + tid * ZN_STR;
        float s = 0.0f;
        #pragma unroll 8
        for (int j = 0; j < Qd; ++j) { float v = zr[j]; s = fmaf(v, v, s); }
        fbase[ZSQ + tid] = s;
    }
    __syncthreads();

    // ================= Phase 2: mma.sync bf16 x3 ===========================
    const int kw = wid & 3;          // k-subtile (16 rows) within 64-row tile
    const int nw = wid >> 2;         // n-group: cols nw*32 .. +31
    const int g  = lane >> 2;
    const int t  = lane & 3;

    float zsqr[8];
    #pragma unroll
    for (int nt = 0; nt < 4; ++nt)
        #pragma unroll
        for (int e = 0; e < 2; ++e)
            zsqr[nt * 2 + e] = fbase[ZSQ + nw * 32 + nt * 8 + 2 * t + e];

    float minv[8];
    int   mini[8];
    #pragma unroll
    for (int i = 0; i < 8; ++i) { minv[i] = 3.402823466e38f; mini[i] = 0; }

    // packed-bf16 B row pointers (row = nw*32 + nt*8 + g, offset 2t words)
    const uint32_t* zbh_r[4];
    const uint32_t* zbl_r[4];
    #pragma unroll
    for (int nt = 0; nt < 4; ++nt) {
        const int n = nw * 32 + nt * 8 + g;
        zbh_r[nt] = reinterpret_cast<const uint32_t*>(fbase + ZBH) +
                    n * ZB_STR + 2 * t;
        zbl_r[nt] = reinterpret_cast<const uint32_t*>(fbase + ZBL) +
                    n * ZB_STR + 2 * t;
    }

    for (int tl = 0; tl < NTILES; ++tl) {
        if (tl < NTILES - 1) cp_wait1(); else cp_wait0();
        __syncthreads();

        const int bufo = (tl & 1) * 8192;
        const uint4* AH4 = reinterpret_cast<const uint4*>(fbase + P_A + bufo) +
                           kw * 256 + lane;
        const uint4* AL4 = AH4 + 1024;   // +4096 words

        float Chh[4][4], Cc[4][4];
        #pragma unroll
        for (int i = 0; i < 4; ++i)
            #pragma unroll
            for (int j = 0; j < 4; ++j) { Chh[i][j] = 0.0f; Cc[i][j] = 0.0f; }

        #pragma unroll
        for (int s = 0; s < 8; ++s) {
            const uint4 ahv = AH4[s * 32];
            const uint4 alv = AL4[s * 32];
            const uint32_t ah[4] = {ahv.x, ahv.y, ahv.z, ahv.w};
            const uint32_t al[4] = {alv.x, alv.y, alv.z, alv.w};
            #pragma unroll
            for (int nt = 0; nt < 4; ++nt) {
                const uint2 bh =
                    *reinterpret_cast<const uint2*>(zbh_r[nt] + s * 8);
                const uint2 bl =
                    *reinterpret_cast<const uint2*>(zbl_r[nt] + s * 8);
                mma_bf16(Cc[nt],  ah, bl.x, bl.y);   // Ah*Bl
                mma_bf16(Cc[nt],  al, bh.x, bh.y);   // Al*Bh
                mma_bf16(Chh[nt], ah, bh.x, bh.y);   // Ah*Bh
            }
        }

        // epilogue: d2 = zsq - 2*(hh+corr) + emb_sq, thread-local argmin
        const int k0 = tl * KTile + kw * 16;
        const float e0 = __ldg(&d_emb_sq[k0 + g]);
        const float e8 = __ldg(&d_emb_sq[k0 + g + 8]);
        #pragma unroll
        for (int nt = 0; nt < 4; ++nt)
            #pragma unroll
            for (int e = 0; e < 2; ++e) {
                const int i = nt * 2 + e;
                const float cr0 = Chh[nt][e] + Cc[nt][e];
                const float cr8 = Chh[nt][2 + e] + Cc[nt][2 + e];
                float d2 = fmaf(-2.0f, cr0, zsqr[i]) + e0;
                if (d2 < minv[i]) { minv[i] = d2; mini[i] = k0 + g; }
                d2 = fmaf(-2.0f, cr8, zsqr[i]) + e8;
                if (d2 < minv[i]) { minv[i] = d2; mini[i] = k0 + g + 8; }
            }

        __syncthreads();   // all warps done with buffer (tl&1) before restage
        if (tl + 2 < NTILES) {
            const int nxt = tl + 2;
            const uint32_t* sH = d_ebAH + (size_t)nxt * 4096;
            const uint32_t* sL = d_ebAL + (size_t)nxt * 4096;
            const uint32_t dst = smemA_u + (uint32_t)(tl & 1) * 32768u;
            #pragma unroll
            for (int c0 = 0; c0 < 1024; c0 += 512) {
                int c = tid + c0;
                cp_async16(dst + (uint32_t)c * 16u, sH + c * 4);
                cp_async16(dst + 16384u + (uint32_t)c * 16u, sL + c * 4);
            }
            cp_commit();
        }
    }
    __syncthreads();

    // ====== cross-thread top-2 reduce + exact fp32 rescore per column ======
    {
        float* rv = fbase + P_A;                         // [32 slots][128 n]
        int*   ri = reinterpret_cast<int*>(fbase + P_A + 4096);
        const int slot = kw * 8 + g;
        #pragma unroll
        for (int nt = 0; nt < 4; ++nt)
            #pragma unroll
            for (int e = 0; e < 2; ++e) {
                const int n = nw * 32 + nt * 8 + 2 * t + e;
                rv[slot * 128 + n] = minv[nt * 2 + e];
                ri[slot * 128 + n] = mini[nt * 2 + e];
            }
        __syncthreads();
        if (tid < 128) {
            float v1 = 3.402823466e38f, v2 = 3.402823466e38f;
            int   i1 = 0, i2 = 0;
            #pragma unroll
            for (int sl = 0; sl < 32; ++sl) {
                const float v  = rv[sl * 128 + tid];
                const int   ix = ri[sl * 128 + tid];
                if (v < v1 || (v == v1 && ix < i1)) {
                    v2 = v1; i2 = i1; v1 = v; i1 = ix;
                } else if (v < v2 || (v == v2 && ix < i2)) {
                    v2 = v; i2 = ix;
                }
            }
            // exact fp32 rescore of both candidates (sequential over q)
            const float* zr = fbase + P_ZE + tid * ZN_STR;
            const float* e1 = emb + (size_t)i1 * Qd;
            const float* e2 = emb + (size_t)i2 * Qd;
            float dot1 = 0.0f, dot2 = 0.0f;
            #pragma unroll 8
            for (int q = 0; q < Qd; ++q) {
                const int p = (q & ~7) + 2 * (q & 3) + ((q >> 2) & 1);
                const float zv = zr[p];
                dot1 = fmaf(e1[q], zv, dot1);
                dot2 = fmaf(e2[q], zv, dot2);
            }
            const float zsqn = fbase[ZSQ + tid];
            const float da = fmaf(-2.0f, dot1, zsqn) + __ldg(&d_emb_sq[i1]);
            const float db = fmaf(-2.0f, dot2, zsqn) + __ldg(&d_emb_sq[i2]);
            int best;
            if (i1 < i2) best = (db < da) ? i2 : i1;   // tie -> lower index
            else         best = (da < db) ? i1 : i2;
            reinterpret_cast<int*>(fbase + IDX)[tid] = best;
        }
        __syncthreads();
    }

    // ============== gather: out[b][q][n] = emb[idx[n]][q] ==================
    // gather buffer reuses the (now dead) fp32 ze region at fbase+0:
    // 128 x 129 = 16512 floats < 17408.
    {
        const int* idx_s = reinterpret_cast<const int*>(fbase + IDX);
        float* gbuf = fbase;
        for (int i = tid; i < Qd * TN; i += THREADS) {
            int n = i >> 7, q = i & 127;
            gbuf[n * 129 + q] = emb[(size_t)idx_s[n] * Qd + q];
        }
        __syncthreads();
        for (int i = tid; i < Qd * TN; i += THREADS) {
            int q = i >> 7, n = i & 127;
            out[((size_t)b * Qd + q) * Nn + n0b + n] = gbuf[n * 129 + q];
        }
    }
}

// ---------------------------------------------------------------------------
extern "C" void kernel_launch(void* const* d_in, const int* in_sizes, int n_in,
                              void* d_out, int out_size) {
    const float* z = nullptr; const float* W = nullptr; const float* emb = nullptr;
    for (int i = 0; i < n_in; ++i) {
        if (in_sizes[i] == Bn * CIN * Nn)   z   = (const float*)d_in[i];
        else if (in_sizes[i] == Qd * CIN)   W   = (const float*)d_in[i];
        else if (in_sizes[i] == Kn * Qd)    emb = (const float*)d_in[i];
    }
    float* out = (float*)d_out;

    cudaFuncSetAttribute(vq_main_kernel,
                         cudaFuncAttributeMaxDynamicSharedMemorySize, SMEM_BYTES);

    embsq_kernel<<<Kn * 32 / 256, 256>>>(emb);
    emb_pack_kernel<<<(Kn * 64 + 255) / 256, 256>>>(emb);
    dim3 grid(Nn / TN, Bn);
    vq_main_kernel<<<grid, THREADS, SMEM_BYTES>>>(z, W, emb, out);
}

// round 9
// speedup vs baseline: 1.6786x; 1.0589x over previous
#include <cuda_runtime.h>
#include <cuda_bf16.h>
#include <cstdint>

// ---------------------------------------------------------------------------
// VQ_16243566313849 round 9: phase-2 mma.sync m16n8k16 bf16 3-term emulation,
// restructured for shared-bandwidth: KTile=128 (warp = 32k x 32n, kb in {0,1})
// halves cross-warp fragment duplication; B fetched as single LDS.128 of
// interleaved [bh0,bh1,bl0,bl1]; fp32 ze lives in a gmem scratch (rescore
// reads it back through L2). Phase-1 stays FFMA2. Top-2 exact-fp32 rescore.
// ---------------------------------------------------------------------------

namespace {
constexpr int Bn  = 8;
constexpr int CIN = 768;
constexpr int Qd  = 128;
constexpr int Kn  = 4096;
constexpr int Nn  = 4096;

constexpr int TN      = 128;
constexpr int KTile   = 128;           // codebook rows per stage
constexpr int NTILES  = Kn / KTile;    // 32
constexpr int THREADS = 512;
constexpr int CK      = 32;            // phase-1 c chunk
constexpr int ZE_STR  = 132;           // phase-1 Wt/zt stride
constexpr int ZB_STR  = 144;           // interleaved bf16 ze row stride (words)

// ---- smem word offsets ----
constexpr int P_ZB = 0;                        // 128 x 144 words (aliases Wt/zt in ph1)
constexpr int ZSQ  = 128 * ZB_STR;             // 18432, 128 words
constexpr int IDX  = ZSQ + 128;                // 18560, 128 words
constexpr int ZSC  = IDX + 128;                // 18688, 2048 words (zsq partials)
constexpr int P_A  = ZSC + 2048;               // 20736: 2 bufs x 16384 words
constexpr int SMEM_FLOATS = P_A + 32768;       // 53504
constexpr int SMEM_BYTES  = SMEM_FLOATS * 4;   // 214016 -> 1 block/SM
}

__device__ float    d_emb_sq[Kn];
__device__ uint32_t d_ebAH[(size_t)Kn * 64];   // frag-packed emb hi (bf16x2)
__device__ uint32_t d_ebAL[(size_t)Kn * 64];   // frag-packed emb lo (bf16x2)
__device__ float    d_zef[(size_t)256 * 128 * 128];  // fp32 ze scratch [blk][q][n]

// ---------------- asm helpers ----------------------------------------------
__device__ __forceinline__ void fma2(unsigned long long& acc,
                                     unsigned long long a,
                                     unsigned long long b) {
    asm("fma.rn.f32x2 %0, %1, %2, %0;" : "+l"(acc) : "l"(a), "l"(b));
}
__device__ __forceinline__ unsigned long long dup2(float x) {
    unsigned long long r;
    unsigned int u = __float_as_uint(x);
    asm("mov.b64 %0, {%1, %1};" : "=l"(r) : "r"(u));
    return r;
}
__device__ __forceinline__ void unpack2(float& lo, float& hi,
                                        unsigned long long v) {
    unsigned int a, b2;
    asm("mov.b64 {%0, %1}, %2;" : "=r"(a), "=r"(b2) : "l"(v));
    lo = __uint_as_float(a); hi = __uint_as_float(b2);
}
__device__ __forceinline__ uint32_t smem_u32(const void* p) {
    uint32_t a;
    asm("{ .reg .u64 t; cvta.to.shared.u64 t, %1; cvt.u32.u64 %0, t; }"
        : "=r"(a) : "l"(p));
    return a;
}
__device__ __forceinline__ void cp_async16(uint32_t dst, const void* src) {
    asm volatile("cp.async.cg.shared.global [%0], [%1], 16;"
                 :: "r"(dst), "l"(src) : "memory");
}
__device__ __forceinline__ void cp_commit() {
    asm volatile("cp.async.commit_group;" ::: "memory");
}
__device__ __forceinline__ void cp_wait1() {
    asm volatile("cp.async.wait_group 1;" ::: "memory");
}
__device__ __forceinline__ void cp_wait0() {
    asm volatile("cp.async.wait_group 0;" ::: "memory");
}
__device__ __forceinline__ void mma_bf16(float c[4], const uint32_t a[4],
                                         uint32_t b0, uint32_t b1) {
    asm("mma.sync.aligned.m16n8k16.row.col.f32.bf16.bf16.f32 "
        "{%0,%1,%2,%3}, {%4,%5,%6,%7}, {%8,%9}, {%0,%1,%2,%3};"
        : "+f"(c[0]), "+f"(c[1]), "+f"(c[2]), "+f"(c[3])
        : "r"(a[0]), "r"(a[1]), "r"(a[2]), "r"(a[3]), "r"(b0), "r"(b1));
}

// ---------------- prologue kernels ------------------------------------------
__global__ void embsq_kernel(const float* __restrict__ emb) {
    int w = (blockIdx.x * blockDim.x + threadIdx.x) >> 5;
    int lane = threadIdx.x & 31;
    if (w >= Kn) return;
    const float* row = emb + (size_t)w * Qd;
    float s = 0.0f;
    #pragma unroll
    for (int j = 0; j < Qd / 32; ++j) { float v = row[lane + j * 32]; s = fmaf(v, v, s); }
    #pragma unroll
    for (int off = 16; off > 0; off >>= 1) s += __shfl_down_sync(0xffffffffu, s, off);
    if (lane == 0) d_emb_sq[w] = s;
}

// Pack emb into m16n8k16 A-fragment order, bf16 hi/lo (uint32 = 2 bf16).
// Layout: [kt64 64][ksub 4][s 8][lane 32][r 4]; lane=(g,t): reg r covers
// row = base + g + 8*(r&1), q pair = s*16 + 2t + 8*(r>>1) .. +1.
__global__ void emb_pack_kernel(const float* __restrict__ emb) {
    int o = blockIdx.x * blockDim.x + threadIdx.x;
    if (o >= Kn * 64) return;
    int kt = o >> 12, r1 = o & 4095;
    int ksub = r1 >> 10, r2 = r1 & 1023;
    int s = r2 >> 7, r3 = r2 & 127;
    int lane = r3 >> 2, r = r3 & 3;
    int g = lane >> 2, t = lane & 3;
    int row = kt * 64 + ksub * 16 + g + 8 * (r & 1);
    int q0  = s * 16 + 2 * t + 8 * (r >> 1);
    float v0 = emb[row * Qd + q0];
    float v1 = emb[row * Qd + q0 + 1];
    __nv_bfloat16 h0 = __float2bfloat16(v0), h1 = __float2bfloat16(v1);
    __nv_bfloat16 l0 = __float2bfloat16(v0 - __bfloat162float(h0));
    __nv_bfloat16 l1 = __float2bfloat16(v1 - __bfloat162float(h1));
    d_ebAH[o] = (uint32_t)__bfloat16_as_ushort(h0) |
                ((uint32_t)__bfloat16_as_ushort(h1) << 16);
    d_ebAL[o] = (uint32_t)__bfloat16_as_ushort(l0) |
                ((uint32_t)__bfloat16_as_ushort(l1) << 16);
}

// ---------------- main kernel -----------------------------------------------
__global__ void __launch_bounds__(THREADS, 1)
vq_main_kernel(const float* __restrict__ z, const float* __restrict__ W,
               const float* __restrict__ emb, float* __restrict__ out) {
    extern __shared__ float fbase[];
    const uint32_t smemA_u = smem_u32(fbase) + (uint32_t)P_A * 4u;

    const int tid  = threadIdx.x;
    const int wid  = tid >> 5;
    const int lane = tid & 31;
    const int b    = blockIdx.y;
    const int n0b  = blockIdx.x * TN;
    const int bid  = b * (Nn / TN) + blockIdx.x;
    float* zef = d_zef + (size_t)bid * 16384;   // [q][n] fp32 ze scratch

    // -------- prefetch A tiles 0 and 1 (P_A free during phase 1) ----------
    {
        #pragma unroll
        for (int tl = 0; tl < 2; ++tl) {
            const uint32_t* sH = d_ebAH + (size_t)tl * 8192;
            const uint32_t* sL = d_ebAL + (size_t)tl * 8192;
            const uint32_t dst = smemA_u + (uint32_t)tl * 65536u;
            #pragma unroll
            for (int k = 0; k < 4; ++k) {
                int c = tid + k * 512;
                cp_async16(dst + (uint32_t)c * 16u, sH + c * 4);
                cp_async16(dst + 32768u + (uint32_t)c * 16u, sL + c * 4);
            }
            cp_commit();
        }
    }

    // ================= Phase 1: ze = W @ z[b] tile (FFMA2) ==================
    {
        float* Wt = fbase + P_ZB;                 // [c][q] stride ZE_STR
        float* zt = fbase + P_ZB + CK * ZE_STR;   // [c][n] stride ZE_STR
        const int ty1 = tid >> 5;                 // q rows ty1*8..+7
        const int tx1 = tid & 31;                 // n cols tx1*4..+3

        unsigned long long acc1[4][4];
        #pragma unroll
        for (int i = 0; i < 4; ++i)
            #pragma unroll
            for (int j = 0; j < 4; ++j) acc1[i][j] = 0ull;

        for (int c0 = 0; c0 < CIN; c0 += CK) {
            for (int i = tid; i < CK * Qd; i += THREADS) {
                int c = i & (CK - 1);
                int q = i >> 5;
                Wt[c * ZE_STR + q] = W[q * CIN + c0 + c];
            }
            const float* zsrc = z + ((size_t)b * CIN + c0) * Nn + n0b;
            for (int i = tid; i < CK * TN; i += THREADS) {
                int r = i >> 7, nn = i & 127;
                zt[r * ZE_STR + nn] = zsrc[(size_t)r * Nn + nn];
            }
            __syncthreads();
            #pragma unroll 4
            for (int c = 0; c < CK; ++c) {
                const ulonglong2 ap0 =
                    *reinterpret_cast<const ulonglong2*>(Wt + c * ZE_STR + ty1 * 8);
                const ulonglong2 ap1 =
                    *reinterpret_cast<const ulonglong2*>(Wt + c * ZE_STR + ty1 * 8 + 4);
                const float4 bv =
                    *reinterpret_cast<const float4*>(zt + c * ZE_STR + tx1 * 4);
                const unsigned long long bd0 = dup2(bv.x), bd1 = dup2(bv.y);
                const unsigned long long bd2 = dup2(bv.z), bd3 = dup2(bv.w);
                fma2(acc1[0][0], ap0.x, bd0); fma2(acc1[0][1], ap0.x, bd1);
                fma2(acc1[0][2], ap0.x, bd2); fma2(acc1[0][3], ap0.x, bd3);
                fma2(acc1[1][0], ap0.y, bd0); fma2(acc1[1][1], ap0.y, bd1);
                fma2(acc1[1][2], ap0.y, bd2); fma2(acc1[1][3], ap0.y, bd3);
                fma2(acc1[2][0], ap1.x, bd0); fma2(acc1[2][1], ap1.x, bd1);
                fma2(acc1[2][2], ap1.x, bd2); fma2(acc1[2][3], ap1.x, bd3);
                fma2(acc1[3][0], ap1.y, bd0); fma2(acc1[3][1], ap1.y, bd1);
                fma2(acc1[3][2], ap1.y, bd2); fma2(acc1[3][3], ap1.y, bd3);
            }
            __syncthreads();   // Wt/zt dead after last iteration
        }
        // epilogue: gmem fp32 ze [q][n] (coalesced), interleaved bf16 ZB in
        // smem, and per-n zsq partials.
        ushort* zb16 = reinterpret_cast<ushort*>(fbase + P_ZB);
        float psum[4] = {0.f, 0.f, 0.f, 0.f};
        #pragma unroll
        for (int qp = 0; qp < 4; ++qp) {
            const int qb = ty1 * 8 + 2 * qp;
            #pragma unroll
            for (int nn = 0; nn < 4; ++nn) {
                float vlo, vhi; unpack2(vlo, vhi, acc1[qp][nn]);
                const int n = tx1 * 4 + nn;
                #pragma unroll
                for (int h = 0; h < 2; ++h) {
                    const int q = qb + h;
                    const float v = h ? vhi : vlo;
                    zef[q * 128 + n] = v;
                    psum[nn] = fmaf(v, v, psum[nn]);
                    // ZB word layout per row n: [s 8][t 4][h0,h1,l0,l1]
                    const int s2 = q >> 4;
                    const int t2 = (q & 7) >> 1;
                    const int d2 = (q >> 3) & 1;
                    const int e2 = q & 1;
                    const int wbase = s2 * 16 + t2 * 4;
                    __nv_bfloat16 hb = __float2bfloat16(v);
                    __nv_bfloat16 lb =
                        __float2bfloat16(v - __bfloat162float(hb));
                    zb16[n * (2 * ZB_STR) + (wbase + d2) * 2 + e2] =
                        __bfloat16_as_ushort(hb);
                    zb16[n * (2 * ZB_STR) + (wbase + 2 + d2) * 2 + e2] =
                        __bfloat16_as_ushort(lb);
                }
            }
        }
        #pragma unroll
        for (int nn = 0; nn < 4; ++nn)
            fbase[ZSC + ty1 * 128 + tx1 * 4 + nn] = psum[nn];
    }
    __syncthreads();

    // zsq reduce: 16 partials per n
    if (tid < 128) {
        float s = 0.0f;
        #pragma unroll
        for (int j = 0; j < 16; ++j) s += fbase[ZSC + j * 128 + tid];
        fbase[ZSQ + tid] = s;
    }
    __syncthreads();

    // ================= Phase 2: mma.sync bf16 x3, KTile=128 ================
    const int kw = wid & 3;          // 16-row k-subtile within each 64 half
    const int nw = wid >> 2;         // n-group: cols nw*32 .. +31
    const int g  = lane >> 2;
    const int t  = lane & 3;

    float zsqr[8];
    #pragma unroll
    for (int nt = 0; nt < 4; ++nt)
        #pragma unroll
        for (int e = 0; e < 2; ++e)
            zsqr[nt * 2 + e] = fbase[ZSQ + nw * 32 + nt * 8 + 2 * t + e];

    float minv[8];
    int   mini[8];
    #pragma unroll
    for (int i = 0; i < 8; ++i) { minv[i] = 3.402823466e38f; mini[i] = 0; }

    // interleaved B row pointers: words n*144 + 4t, fetched as uint4[s*4]
    const uint4* brow[4];
    #pragma unroll
    for (int nt = 0; nt < 4; ++nt) {
        const int n = nw * 32 + nt * 8 + g;
        brow[nt] = reinterpret_cast<const uint4*>(
            fbase + P_ZB + n * ZB_STR + 4 * t);
    }

    for (int tl = 0; tl < NTILES; ++tl) {
        if (tl < NTILES - 1) cp_wait1(); else cp_wait0();
        __syncthreads();

        const uint4* Abase = reinterpret_cast<const uint4*>(
            fbase + P_A + (tl & 1) * 16384);
        const uint4* AH0 = Abase + kw * 256 + lane;          // kb=0 hi
        const uint4* AH1 = Abase + (kw + 4) * 256 + lane;    // kb=1 hi
        // lo halves at +8192 words = +2048 uint4

        float C0[4][4], C1[4][4];
        #pragma unroll
        for (int i = 0; i < 4; ++i)
            #pragma unroll
            for (int j = 0; j < 4; ++j) { C0[i][j] = 0.0f; C1[i][j] = 0.0f; }

        #pragma unroll
        for (int s = 0; s < 8; ++s) {
            const uint4 ah0v = AH0[s * 32];
            const uint4 al0v = AH0[2048 + s * 32];
            const uint4 ah1v = AH1[s * 32];
            const uint4 al1v = AH1[2048 + s * 32];
            const uint32_t ah0[4] = {ah0v.x, ah0v.y, ah0v.z, ah0v.w};
            const uint32_t al0[4] = {al0v.x, al0v.y, al0v.z, al0v.w};
            const uint32_t ah1[4] = {ah1v.x, ah1v.y, ah1v.z, ah1v.w};
            const uint32_t al1[4] = {al1v.x, al1v.y, al1v.z, al1v.w};
            #pragma unroll
            for (int nt = 0; nt < 4; ++nt) {
                const uint4 w = brow[nt][s * 4];   // {bh0,bh1,bl0,bl1}
                mma_bf16(C0[nt], ah0, w.z, w.w);   // Ah*Bl
                mma_bf16(C0[nt], al0, w.x, w.y);   // Al*Bh
                mma_bf16(C0[nt], ah0, w.x, w.y);   // Ah*Bh
                mma_bf16(C1[nt], ah1, w.z, w.w);
                mma_bf16(C1[nt], al1, w.x, w.y);
                mma_bf16(C1[nt], ah1, w.x, w.y);
            }
        }

        // epilogue: d2 = zsq - 2*cross + emb_sq, thread-local argmin
        const int k0 = tl * KTile + kw * 16;        // kb=0
        const int k1 = k0 + 64;                     // kb=1
        const float e00 = __ldg(&d_emb_sq[k0 + g]);
        const float e08 = __ldg(&d_emb_sq[k0 + g + 8]);
        const float e10 = __ldg(&d_emb_sq[k1 + g]);
        const float e18 = __ldg(&d_emb_sq[k1 + g + 8]);
        #pragma unroll
        for (int nt = 0; nt < 4; ++nt)
            #pragma unroll
            for (int e = 0; e < 2; ++e) {
                const int i = nt * 2 + e;
                float d2 = fmaf(-2.0f, C0[nt][e], zsqr[i]) + e00;
                if (d2 < minv[i]) { minv[i] = d2; mini[i] = k0 + g; }
                d2 = fmaf(-2.0f, C0[nt][2 + e], zsqr[i]) + e08;
                if (d2 < minv[i]) { minv[i] = d2; mini[i] = k0 + g + 8; }
                d2 = fmaf(-2.0f, C1[nt][e], zsqr[i]) + e10;
                if (d2 < minv[i]) { minv[i] = d2; mini[i] = k1 + g; }
                d2 = fmaf(-2.0f, C1[nt][2 + e], zsqr[i]) + e18;
                if (d2 < minv[i]) { minv[i] = d2; mini[i] = k1 + g + 8; }
            }

        __syncthreads();   // all warps done with buffer (tl&1) before restage
        if (tl + 2 < NTILES) {
            const int nxt = tl + 2;
            const uint32_t* sH = d_ebAH + (size_t)nxt * 8192;
            const uint32_t* sL = d_ebAL + (size_t)nxt * 8192;
            const uint32_t dst = smemA_u + (uint32_t)(tl & 1) * 65536u;
            #pragma unroll
            for (int k = 0; k < 4; ++k) {
                int c = tid + k * 512;
                cp_async16(dst + (uint32_t)c * 16u, sH + c * 4);
                cp_async16(dst + 32768u + (uint32_t)c * 16u, sL + c * 4);
            }
            cp_commit();
        }
    }
    __syncthreads();

    // ====== cross-thread top-2 reduce + exact fp32 rescore per column ======
    {
        float* rv = fbase + P_A;                         // [32 slots][128 n]
        int*   ri = reinterpret_cast<int*>(fbase + P_A + 4096);
        const int slot = kw * 8 + g;
        #pragma unroll
        for (int nt = 0; nt < 4; ++nt)
            #pragma unroll
            for (int e = 0; e < 2; ++e) {
                const int n = nw * 32 + nt * 8 + 2 * t + e;
                rv[slot * 128 + n] = minv[nt * 2 + e];
                ri[slot * 128 + n] = mini[nt * 2 + e];
            }
        __syncthreads();
        if (tid < 128) {
            float v1 = 3.402823466e38f, v2 = 3.402823466e38f;
            int   i1 = 0, i2 = 0;
            #pragma unroll
            for (int sl = 0; sl < 32; ++sl) {
                const float v  = rv[sl * 128 + tid];
                const int   ix = ri[sl * 128 + tid];
                if (v < v1 || (v == v1 && ix < i1)) {
                    v2 = v1; i2 = i1; v1 = v; i1 = ix;
                } else if (v < v2 || (v == v2 && ix < i2)) {
                    v2 = v; i2 = ix;
                }
            }
            // exact fp32 rescore of both candidates (ze from gmem/L2)
            const float* e1 = emb + (size_t)i1 * Qd;
            const float* e2 = emb + (size_t)i2 * Qd;
            float dot1 = 0.0f, dot2 = 0.0f;
            #pragma unroll 8
            for (int q = 0; q < Qd; ++q) {
                const float zv = zef[q * 128 + tid];
                dot1 = fmaf(e1[q], zv, dot1);
                dot2 = fmaf(e2[q], zv, dot2);
            }
            const float zsqn = fbase[ZSQ + tid];
            const float da = fmaf(-2.0f, dot1, zsqn) + __ldg(&d_emb_sq[i1]);
            const float db = fmaf(-2.0f, dot2, zsqn) + __ldg(&d_emb_sq[i2]);
            int best;
            if (i1 < i2) best = (db < da) ? i2 : i1;   // tie -> lower index
            else         best = (da < db) ? i1 : i2;
            reinterpret_cast<int*>(fbase + IDX)[tid] = best;
        }
        __syncthreads();
    }

    // ============== gather: out[b][q][n] = emb[idx[n]][q] ==================
    {
        const int* idx_s = reinterpret_cast<const int*>(fbase + IDX);
        float* gbuf = fbase + P_A;   // 128 x 129 (A region dead)
        for (int i = tid; i < Qd * TN; i += THREADS) {
            int n = i >> 7, q = i & 127;
            gbuf[n * 129 + q] = emb[(size_t)idx_s[n] * Qd + q];
        }
        __syncthreads();
        for (int i = tid; i < Qd * TN; i += THREADS) {
            int q = i >> 7, n = i & 127;
            out[((size_t)b * Qd + q) * Nn + n0b + n] = gbuf[n * 129 + q];
        }
    }
}

// ---------------------------------------------------------------------------
extern "C" void kernel_launch(void* const* d_in, const int* in_sizes, int n_in,
                              void* d_out, int out_size) {
    const float* z = nullptr; const float* W = nullptr; const float* emb = nullptr;
    for (int i = 0; i < n_in; ++i) {
        if (in_sizes[i] == Bn * CIN * Nn)   z   = (const float*)d_in[i];
        else if (in_sizes[i] == Qd * CIN)   W   = (const float*)d_in[i];
        else if (in_sizes[i] == Kn * Qd)    emb = (const float*)d_in[i];
    }
    float* out = (float*)d_out;

    cudaFuncSetAttribute(vq_main_kernel,
                         cudaFuncAttributeMaxDynamicSharedMemorySize, SMEM_BYTES);

    embsq_kernel<<<Kn * 32 / 256, 256>>>(emb);
    emb_pack_kernel<<<(Kn * 64 + 255) / 256, 256>>>(emb);
    dim3 grid(Nn / TN, Bn);
    vq_main_kernel<<<grid, THREADS, SMEM_BYTES>>>(z, W, emb, out);
}

// round 13
// speedup vs baseline: 1.8598x; 1.1079x over previous
#include <cuda_runtime.h>
#include <cuda_fp16.h>
#include <cstdint>

// ---------------------------------------------------------------------------
// VQ_16243566313849 round 13: fp16 single-term mma.sync m16n8k16 for phase-2
// (issue-bound: fewer mma instructions = the win), per-thread top-2 slots +
// global top-4 exact-fp32 rescore for correctness. Phase-1 on FFMA2.
// R13 fix vs R12: B-tile load index now mirrors the store exactly --
//   idx4 = (n*16 + s2*4 + t) ^ ((n&1)<<2)
// (R12 applied the XOR before adding s2*4; for odd n this read the wrong
// k-step slot and bled into the next row, corrupting half the columns.)
// ---------------------------------------------------------------------------

namespace {
constexpr int Bn  = 8;
constexpr int CIN = 768;
constexpr int Qd  = 128;
constexpr int Kn  = 4096;
constexpr int Nn  = 4096;

constexpr int TN      = 128;
constexpr int KTile   = 128;           // codebook rows per stage
constexpr int NTILES  = Kn / KTile;    // 32
constexpr int THREADS = 512;
constexpr int CK      = 32;            // phase-1 c chunk
constexpr int ZE_STR  = 132;           // phase-1 Wt/zt stride

// ---- smem word offsets ----
constexpr int P_ZB = 0;                // fp16 B tiles (8192 words); Wt/zt in ph1
constexpr int ZSQ  = 8448;             // 128 words
constexpr int IDX  = 8576;             // 128 words
constexpr int ZSC  = 8704;             // 2048 words (zsq partials)
constexpr int P_A  = 10752;            // 2 bufs x 8192 words (fp16 A tiles)
constexpr int SMEM_FLOATS = P_A + 16384;       // 27136
constexpr int SMEM_BYTES  = SMEM_FLOATS * 4;   // 108544
}

__device__ float    d_emb_sq[Kn];
__device__ uint32_t d_eA16[(size_t)Kn * 64];         // frag-packed emb fp16x2
__device__ float    d_zef[(size_t)256 * 128 * 128];  // fp32 ze scratch [blk][q][n]

// ---------------- asm helpers ----------------------------------------------
__device__ __forceinline__ void fma2(unsigned long long& acc,
                                     unsigned long long a,
                                     unsigned long long b) {
    asm("fma.rn.f32x2 %0, %1, %2, %0;" : "+l"(acc) : "l"(a), "l"(b));
}
__device__ __forceinline__ unsigned long long dup2(float x) {
    unsigned long long r;
    unsigned int u = __float_as_uint(x);
    asm("mov.b64 %0, {%1, %1};" : "=l"(r) : "r"(u));
    return r;
}
__device__ __forceinline__ void unpack2(float& lo, float& hi,
                                        unsigned long long v) {
    unsigned int a, b2;
    asm("mov.b64 {%0, %1}, %2;" : "=r"(a), "=r"(b2) : "l"(v));
    lo = __uint_as_float(a); hi = __uint_as_float(b2);
}
__device__ __forceinline__ uint32_t smem_u32(const void* p) {
    uint32_t a;
    asm("{ .reg .u64 t; cvta.to.shared.u64 t, %1; cvt.u32.u64 %0, t; }"
        : "=r"(a) : "l"(p));
    return a;
}
__device__ __forceinline__ void cp_async16(uint32_t dst, const void* src) {
    asm volatile("cp.async.cg.shared.global [%0], [%1], 16;"
                 :: "r"(dst), "l"(src) : "memory");
}
__device__ __forceinline__ void cp_commit() {
    asm volatile("cp.async.commit_group;" ::: "memory");
}
__device__ __forceinline__ void cp_wait1() {
    asm volatile("cp.async.wait_group 1;" ::: "memory");
}
__device__ __forceinline__ void cp_wait0() {
    asm volatile("cp.async.wait_group 0;" ::: "memory");
}
__device__ __forceinline__ void mma_f16(float c[4], const uint4& a,
                                        uint32_t b0, uint32_t b1) {
    asm("mma.sync.aligned.m16n8k16.row.col.f32.f16.f16.f32 "
        "{%0,%1,%2,%3}, {%4,%5,%6,%7}, {%8,%9}, {%0,%1,%2,%3};"
        : "+f"(c[0]), "+f"(c[1]), "+f"(c[2]), "+f"(c[3])
        : "r"(a.x), "r"(a.y), "r"(a.z), "r"(a.w), "r"(b0), "r"(b1));
}

// ---------------- prologue kernels ------------------------------------------
__global__ void embsq_kernel(const float* __restrict__ emb) {
    int w = (blockIdx.x * blockDim.x + threadIdx.x) >> 5;
    int lane = threadIdx.x & 31;
    if (w >= Kn) return;
    const float* row = emb + (size_t)w * Qd;
    float s = 0.0f;
    #pragma unroll
    for (int j = 0; j < Qd / 32; ++j) { float v = row[lane + j * 32]; s = fmaf(v, v, s); }
    #pragma unroll
    for (int off = 16; off > 0; off >>= 1) s += __shfl_down_sync(0xffffffffu, s, off);
    if (lane == 0) d_emb_sq[w] = s;
}

// Pack emb into m16n8k16 A-fragment order, fp16 (uint32 = 2 fp16, even q low).
// [kt64 64][ksub 4][s 8][lane 32][r 4]; lane=(g,t): reg r covers
// row = base + g + 8*(r&1), q pair = s*16 + 2t + 8*(r>>1) .. +1.
__global__ void emb_pack_kernel(const float* __restrict__ emb) {
    int o = blockIdx.x * blockDim.x + threadIdx.x;
    if (o >= Kn * 64) return;
    int kt = o >> 12, r1 = o & 4095;
    int ksub = r1 >> 10, r2 = r1 & 1023;
    int s = r2 >> 7, r3 = r2 & 127;
    int lane = r3 >> 2, r = r3 & 3;
    int g = lane >> 2, t = lane & 3;
    int row = kt * 64 + ksub * 16 + g + 8 * (r & 1);
    int q0  = s * 16 + 2 * t + 8 * (r >> 1);
    __half h0 = __float2half(emb[row * Qd + q0]);
    __half h1 = __float2half(emb[row * Qd + q0 + 1]);
    d_eA16[o] = (uint32_t)__half_as_ushort(h0) |
                ((uint32_t)__half_as_ushort(h1) << 16);
}

// ---------------- main kernel -----------------------------------------------
__global__ void __launch_bounds__(THREADS, 1)
vq_main_kernel(const float* __restrict__ z, const float* __restrict__ W,
               const float* __restrict__ emb, float* __restrict__ out) {
    extern __shared__ float fbase[];
    const uint32_t smemA_u = smem_u32(fbase) + (uint32_t)P_A * 4u;

    const int tid  = threadIdx.x;
    const int wid  = tid >> 5;
    const int lane = tid & 31;
    const int b    = blockIdx.y;
    const int n0b  = blockIdx.x * TN;
    const int bid  = b * (Nn / TN) + blockIdx.x;
    float* zef = d_zef + (size_t)bid * 16384;   // [q][n] fp32 ze scratch

    // -------- prefetch A tiles 0 and 1 (P_A free during phase 1) ----------
    {
        #pragma unroll
        for (int tl = 0; tl < 2; ++tl) {
            const uint32_t* sA = d_eA16 + (size_t)tl * 8192;
            const uint32_t dst = smemA_u + (uint32_t)tl * 32768u;
            #pragma unroll
            for (int k = 0; k < 4; ++k) {
                int c = tid + k * 512;
                cp_async16(dst + (uint32_t)c * 16u, sA + c * 4);
            }
            cp_commit();
        }
    }

    // ================= Phase 1: ze = W @ z[b] tile (FFMA2) ==================
    {
        float* Wt = fbase;                 // [c][q] stride ZE_STR
        float* zt = fbase + CK * ZE_STR;   // [c][n] stride ZE_STR
        const int ty1 = tid >> 5;          // q rows ty1*8..+7
        const int tx1 = tid & 31;          // n cols tx1*4..+3

        unsigned long long acc1[4][4];
        #pragma unroll
        for (int i = 0; i < 4; ++i)
            #pragma unroll
            for (int j = 0; j < 4; ++j) acc1[i][j] = 0ull;

        for (int c0 = 0; c0 < CIN; c0 += CK) {
            for (int i = tid; i < CK * Qd; i += THREADS) {
                int c = i & (CK - 1);
                int q = i >> 5;
                Wt[c * ZE_STR + q] = W[q * CIN + c0 + c];
            }
            const float* zsrc = z + ((size_t)b * CIN + c0) * Nn + n0b;
            for (int i = tid; i < CK * TN; i += THREADS) {
                int r = i >> 7, nn = i & 127;
                zt[r * ZE_STR + nn] = zsrc[(size_t)r * Nn + nn];
            }
            __syncthreads();
            #pragma unroll 4
            for (int c = 0; c < CK; ++c) {
                const ulonglong2 ap0 =
                    *reinterpret_cast<const ulonglong2*>(Wt + c * ZE_STR + ty1 * 8);
                const ulonglong2 ap1 =
                    *reinterpret_cast<const ulonglong2*>(Wt + c * ZE_STR + ty1 * 8 + 4);
                const float4 bv =
                    *reinterpret_cast<const float4*>(zt + c * ZE_STR + tx1 * 4);
                const unsigned long long bd0 = dup2(bv.x), bd1 = dup2(bv.y);
                const unsigned long long bd2 = dup2(bv.z), bd3 = dup2(bv.w);
                fma2(acc1[0][0], ap0.x, bd0); fma2(acc1[0][1], ap0.x, bd1);
                fma2(acc1[0][2], ap0.x, bd2); fma2(acc1[0][3], ap0.x, bd3);
                fma2(acc1[1][0], ap0.y, bd0); fma2(acc1[1][1], ap0.y, bd1);
                fma2(acc1[1][2], ap0.y, bd2); fma2(acc1[1][3], ap0.y, bd3);
                fma2(acc1[2][0], ap1.x, bd0); fma2(acc1[2][1], ap1.x, bd1);
                fma2(acc1[2][2], ap1.x, bd2); fma2(acc1[2][3], ap1.x, bd3);
                fma2(acc1[3][0], ap1.y, bd0); fma2(acc1[3][1], ap1.y, bd1);
                fma2(acc1[3][2], ap1.y, bd2); fma2(acc1[3][3], ap1.y, bd3);
            }
            __syncthreads();   // Wt/zt dead after last iteration
        }
        // epilogue: gmem fp32 ze [q][n], fp16 ZB (swizzled) in smem, zsq
        // partials. ZB uint4 index for q-pair (q0 even):
        //   s=q0>>4, s2=s>>1, odd=s&1, d=(q0>>3)&1, t2=(q0&7)>>1
        //   idx4 = (n*16 + s2*4 + t2) ^ ((n&1)<<2); word = odd*2 + d
        uint32_t* zb32 = reinterpret_cast<uint32_t*>(fbase + P_ZB);
        float psum[4] = {0.f, 0.f, 0.f, 0.f};
        #pragma unroll
        for (int qp = 0; qp < 4; ++qp) {
            const int qb = ty1 * 8 + 2 * qp;          // even
            const int s  = qb >> 4;
            const int s2 = s >> 1;
            const int od = s & 1;
            const int d  = (qb >> 3) & 1;
            const int t2 = (qb & 7) >> 1;
            #pragma unroll
            for (int nn = 0; nn < 4; ++nn) {
                float vlo, vhi; unpack2(vlo, vhi, acc1[qp][nn]);
                const int n = tx1 * 4 + nn;
                zef[qb * 128 + n]       = vlo;
                zef[(qb + 1) * 128 + n] = vhi;
                psum[nn] = fmaf(vlo, vlo, psum[nn]);
                psum[nn] = fmaf(vhi, vhi, psum[nn]);
                const int idx4 = (n * 16 + s2 * 4 + t2) ^ ((n & 1) << 2);
                __half h0 = __float2half(vlo);
                __half h1 = __float2half(vhi);
                zb32[idx4 * 4 + od * 2 + d] =
                    (uint32_t)__half_as_ushort(h0) |
                    ((uint32_t)__half_as_ushort(h1) << 16);
            }
        }
        #pragma unroll
        for (int nn = 0; nn < 4; ++nn)
            fbase[ZSC + ty1 * 128 + tx1 * 4 + nn] = psum[nn];
    }
    __syncthreads();

    // zsq reduce: 16 partials per n
    if (tid < 128) {
        float s = 0.0f;
        #pragma unroll
        for (int j = 0; j < 16; ++j) s += fbase[ZSC + j * 128 + tid];
        fbase[ZSQ + tid] = s;
    }
    __syncthreads();

    // ================= Phase 2: single-term fp16 mma =======================
    const int kw = wid & 3;          // 16-row k-subtile within each 64 half
    const int nw = wid >> 2;         // n-group: cols nw*32 .. +31
    const int g  = lane >> 2;
    const int t  = lane & 3;

    float zsqr[8];
    #pragma unroll
    for (int nt = 0; nt < 4; ++nt)
        #pragma unroll
        for (int e = 0; e < 2; ++e)
            zsqr[nt * 2 + e] = fbase[ZSQ + nw * 32 + nt * 8 + 2 * t + e];

    float mv1[8], mv2[8];
    int   mi1[8], mi2[8];
    #pragma unroll
    for (int i = 0; i < 8; ++i) {
        mv1[i] = 3.402823466e38f; mv2[i] = 3.402823466e38f;
        mi1[i] = 0; mi2[i] = 0;
    }

    // B load index base per nt: nbase = n*16 + t, parity swizzle sw = (n&1)<<2
    // (full index computed per s2, mirroring the store exactly — R13 fix)
    int nbase[4], nsw[4];
    #pragma unroll
    for (int nt = 0; nt < 4; ++nt) {
        const int n = nw * 32 + nt * 8 + g;
        nbase[nt] = n * 16 + t;
        nsw[nt]   = (n & 1) << 2;
    }
    const uint4* zb4 = reinterpret_cast<const uint4*>(fbase + P_ZB);

    for (int tl = 0; tl < NTILES; ++tl) {
        if (tl < NTILES - 1) cp_wait1(); else cp_wait0();
        __syncthreads();

        const uint4* Abase = reinterpret_cast<const uint4*>(
            fbase + P_A + (tl & 1) * 8192);
        const uint4* A0 = Abase + kw * 256 + lane;         // ksub kw (kb=0)
        const uint4* A1 = Abase + (kw + 4) * 256 + lane;   // ksub kw+4 (kb=1)

        float C0[4][4], C1[4][4];
        #pragma unroll
        for (int i = 0; i < 4; ++i)
            #pragma unroll
            for (int j = 0; j < 4; ++j) { C0[i][j] = 0.0f; C1[i][j] = 0.0f; }

        #pragma unroll
        for (int s2 = 0; s2 < 4; ++s2) {
            const uint4 a0e = A0[(2 * s2) * 32];
            const uint4 a0o = A0[(2 * s2 + 1) * 32];
            const uint4 a1e = A1[(2 * s2) * 32];
            const uint4 a1o = A1[(2 * s2 + 1) * 32];
            #pragma unroll
            for (int nt = 0; nt < 4; ++nt) {
                const uint4 w = zb4[(nbase[nt] + s2 * 4) ^ nsw[nt]];
                mma_f16(C0[nt], a0e, w.x, w.y);   // step s=2*s2
                mma_f16(C0[nt], a0o, w.z, w.w);   // step s=2*s2+1
                mma_f16(C1[nt], a1e, w.x, w.y);
                mma_f16(C1[nt], a1o, w.z, w.w);
            }
        }

        // epilogue: d2, per-thread top-2 per column
        const int k0 = tl * KTile + kw * 16;        // kb=0
        const int k1 = k0 + 64;                     // kb=1
        const float e00 = __ldg(&d_emb_sq[k0 + g]);
        const float e08 = __ldg(&d_emb_sq[k0 + g + 8]);
        const float e10 = __ldg(&d_emb_sq[k1 + g]);
        const float e18 = __ldg(&d_emb_sq[k1 + g + 8]);
        #pragma unroll
        for (int nt = 0; nt < 4; ++nt)
            #pragma unroll
            for (int e = 0; e < 2; ++e) {
                const int i = nt * 2 + e;
                float d2; int k;
                #pragma unroll
                for (int c = 0; c < 4; ++c) {
                    switch (c) {
                        case 0: d2 = fmaf(-2.0f, C0[nt][e], zsqr[i]) + e00;
                                k = k0 + g; break;
                        case 1: d2 = fmaf(-2.0f, C0[nt][2 + e], zsqr[i]) + e08;
                                k = k0 + g + 8; break;
                        case 2: d2 = fmaf(-2.0f, C1[nt][e], zsqr[i]) + e10;
                                k = k1 + g; break;
                        default: d2 = fmaf(-2.0f, C1[nt][2 + e], zsqr[i]) + e18;
                                k = k1 + g + 8; break;
                    }
                    if (d2 < mv1[i]) {
                        mv2[i] = mv1[i]; mi2[i] = mi1[i];
                        mv1[i] = d2;     mi1[i] = k;
                    } else if (d2 < mv2[i]) {
                        mv2[i] = d2; mi2[i] = k;
                    }
                }
            }

        __syncthreads();   // all warps done with buffer (tl&1) before restage
        if (tl + 2 < NTILES) {
            const uint32_t* sA = d_eA16 + (size_t)(tl + 2) * 8192;
            const uint32_t dst = smemA_u + (uint32_t)(tl & 1) * 32768u;
            #pragma unroll
            for (int k = 0; k < 4; ++k) {
                int c = tid + k * 512;
                cp_async16(dst + (uint32_t)c * 16u, sA + c * 4);
            }
            cp_commit();
        }
    }
    __syncthreads();

    // ====== cross-thread top-4 reduce + exact fp32 rescore per column ======
    {
        float* rv = fbase + P_A;                          // [64 slots][128 n]
        int*   ri = reinterpret_cast<int*>(fbase + P_A + 8192);
        const int slot2 = (kw * 8 + g) * 2;
        #pragma unroll
        for (int nt = 0; nt < 4; ++nt)
            #pragma unroll
            for (int e = 0; e < 2; ++e) {
                const int n = nw * 32 + nt * 8 + 2 * t + e;
                rv[slot2 * 128 + n]       = mv1[nt * 2 + e];
                ri[slot2 * 128 + n]       = mi1[nt * 2 + e];
                rv[(slot2 + 1) * 128 + n] = mv2[nt * 2 + e];
                ri[(slot2 + 1) * 128 + n] = mi2[nt * 2 + e];
            }
        __syncthreads();
        if (tid < 128) {
            float bv[4] = {3.402823466e38f, 3.402823466e38f,
                           3.402823466e38f, 3.402823466e38f};
            int   bi[4] = {0, 0, 0, 0};
            for (int sl = 0; sl < 64; ++sl) {
                const float v  = rv[sl * 128 + tid];
                const int   ix = ri[sl * 128 + tid];
                if (v < bv[3] || (v == bv[3] && ix < bi[3])) {
                    bv[3] = v; bi[3] = ix;
                    #pragma unroll
                    for (int j = 3; j > 0; --j) {
                        if (bv[j] < bv[j-1] ||
                            (bv[j] == bv[j-1] && bi[j] < bi[j-1])) {
                            float tv = bv[j]; bv[j] = bv[j-1]; bv[j-1] = tv;
                            int   ti = bi[j]; bi[j] = bi[j-1]; bi[j-1] = ti;
                        }
                    }
                }
            }
            // exact fp32 rescore of 4 candidates (ze from gmem/L2)
            const float* ep[4];
            #pragma unroll
            for (int c = 0; c < 4; ++c) ep[c] = emb + (size_t)bi[c] * Qd;
            float dot[4] = {0.f, 0.f, 0.f, 0.f};
            #pragma unroll 4
            for (int q = 0; q < Qd; ++q) {
                const float zv = zef[q * 128 + tid];
                #pragma unroll
                for (int c = 0; c < 4; ++c)
                    dot[c] = fmaf(ep[c][q], zv, dot[c]);
            }
            const float zsqn = fbase[ZSQ + tid];
            int   best = bi[0];
            float bd = fmaf(-2.0f, dot[0], zsqn) + __ldg(&d_emb_sq[bi[0]]);
            #pragma unroll
            for (int c = 1; c < 4; ++c) {
                const float dc =
                    fmaf(-2.0f, dot[c], zsqn) + __ldg(&d_emb_sq[bi[c]]);
                if (dc < bd || (dc == bd && bi[c] < best)) {
                    bd = dc; best = bi[c];
                }
            }
            reinterpret_cast<int*>(fbase + IDX)[tid] = best;
        }
        __syncthreads();
    }

    // ============== gather: out[b][q][n] = emb[idx[n]][q] ==================
    // gbuf at P_A (dead), stride 128 with XOR swizzle -> conflict-free.
    {
        const int* idx_s = reinterpret_cast<const int*>(fbase + IDX);
        float* gbuf = fbase + P_A;
        for (int i = tid; i < Qd * TN; i += THREADS) {
            int n = i >> 7, q = i & 127;
            gbuf[n * 128 + (q ^ (n & 31))] = emb[(size_t)idx_s[n] * Qd + q];
        }
        __syncthreads();
        for (int i = tid; i < Qd * TN; i += THREADS) {
            int q = i >> 7, n = i & 127;
            out[((size_t)b * Qd + q) * Nn + n0b + n] =
                gbuf[n * 128 + (q ^ (n & 31))];
        }
    }
}

// ---------------------------------------------------------------------------
extern "C" void kernel_launch(void* const* d_in, const int* in_sizes, int n_in,
                              void* d_out, int out_size) {
    const float* z = nullptr; const float* W = nullptr; const float* emb = nullptr;
    for (int i = 0; i < n_in; ++i) {
        if (in_sizes[i] == Bn * CIN * Nn)   z   = (const float*)d_in[i];
        else if (in_sizes[i] == Qd * CIN)   W   = (const float*)d_in[i];
        else if (in_sizes[i] == Kn * Qd)    emb = (const float*)d_in[i];
    }
    float* out = (float*)d_out;

    cudaFuncSetAttribute(vq_main_kernel,
                         cudaFuncAttributeMaxDynamicSharedMemorySize, SMEM_BYTES);

    embsq_kernel<<<Kn * 32 / 256, 256>>>(emb);
    emb_pack_kernel<<<(Kn * 64 + 255) / 256, 256>>>(emb);
    dim3 grid(Nn / TN, Bn);
    vq_main_kernel<<<grid, THREADS, SMEM_BYTES>>>(z, W, emb, out);
}

// round 14
// speedup vs baseline: 1.8843x; 1.0132x over previous
#include <cuda_runtime.h>
#include <cuda_fp16.h>
#include <cstdint>

// ---------------------------------------------------------------------------
// VQ_16243566313849 round 14: same compute as R13 (fp16 single-term m16n8k16
// phase-2 + top-2/top-4 exact-fp32 rescore; FFMA2 phase-1), plus:
//  - prologue kernels merged into ONE prep kernel (period-2 launch pattern so
//    the fixed ncu -s5 -c1 capture lands on vq_main next round)
//  - 3-stage A pipeline: restage buf (tl+2)%3 disjoint from both live bufs ->
//    the per-tile pre-restage __syncthreads is removed (one sync per tile).
// ---------------------------------------------------------------------------

namespace {
constexpr int Bn  = 8;
constexpr int CIN = 768;
constexpr int Qd  = 128;
constexpr int Kn  = 4096;
constexpr int Nn  = 4096;

constexpr int TN      = 128;
constexpr int KTile   = 128;           // codebook rows per stage
constexpr int NTILES  = Kn / KTile;    // 32
constexpr int THREADS = 512;
constexpr int CK      = 32;            // phase-1 c chunk
constexpr int ZE_STR  = 132;           // phase-1 Wt/zt stride

// ---- smem word offsets ----
constexpr int P_ZB = 0;                // fp16 B tiles (8192 words); Wt/zt in ph1
constexpr int ZSQ  = 8448;             // 128 words
constexpr int IDX  = 8576;             // 128 words
constexpr int ZSC  = 8704;             // 2048 words (zsq partials)
constexpr int P_A  = 10752;            // 3 bufs x 8192 words (fp16 A tiles)
constexpr int SMEM_FLOATS = P_A + 3 * 8192;    // 35328
constexpr int SMEM_BYTES  = SMEM_FLOATS * 4;   // 141312
}

__device__ float    d_emb_sq[Kn];
__device__ uint32_t d_eA16[(size_t)Kn * 64];         // frag-packed emb fp16x2
__device__ float    d_zef[(size_t)256 * 128 * 128];  // fp32 ze scratch [blk][q][n]

// ---------------- asm helpers ----------------------------------------------
__device__ __forceinline__ void fma2(unsigned long long& acc,
                                     unsigned long long a,
                                     unsigned long long b) {
    asm("fma.rn.f32x2 %0, %1, %2, %0;" : "+l"(acc) : "l"(a), "l"(b));
}
__device__ __forceinline__ unsigned long long dup2(float x) {
    unsigned long long r;
    unsigned int u = __float_as_uint(x);
    asm("mov.b64 %0, {%1, %1};" : "=l"(r) : "r"(u));
    return r;
}
__device__ __forceinline__ void unpack2(float& lo, float& hi,
                                        unsigned long long v) {
    unsigned int a, b2;
    asm("mov.b64 {%0, %1}, %2;" : "=r"(a), "=r"(b2) : "l"(v));
    lo = __uint_as_float(a); hi = __uint_as_float(b2);
}
__device__ __forceinline__ uint32_t smem_u32(const void* p) {
    uint32_t a;
    asm("{ .reg .u64 t; cvta.to.shared.u64 t, %1; cvt.u32.u64 %0, t; }"
        : "=r"(a) : "l"(p));
    return a;
}
__device__ __forceinline__ void cp_async16(uint32_t dst, const void* src) {
    asm volatile("cp.async.cg.shared.global [%0], [%1], 16;"
                 :: "r"(dst), "l"(src) : "memory");
}
__device__ __forceinline__ void cp_commit() {
    asm volatile("cp.async.commit_group;" ::: "memory");
}
__device__ __forceinline__ void cp_wait1() {
    asm volatile("cp.async.wait_group 1;" ::: "memory");
}
__device__ __forceinline__ void cp_wait0() {
    asm volatile("cp.async.wait_group 0;" ::: "memory");
}
__device__ __forceinline__ void mma_f16(float c[4], const uint4& a,
                                        uint32_t b0, uint32_t b1) {
    asm("mma.sync.aligned.m16n8k16.row.col.f32.f16.f16.f32 "
        "{%0,%1,%2,%3}, {%4,%5,%6,%7}, {%8,%9}, {%0,%1,%2,%3};"
        : "+f"(c[0]), "+f"(c[1]), "+f"(c[2]), "+f"(c[3])
        : "r"(a.x), "r"(a.y), "r"(a.z), "r"(a.w), "r"(b0), "r"(b1));
}

// ---------------- merged prologue kernel ------------------------------------
// blocks [0, 1024): fragment-pack emb -> d_eA16 (fp16x2)
// blocks [1024, 1536): row squared-norms -> d_emb_sq
__global__ void prep_kernel(const float* __restrict__ emb) {
    if (blockIdx.x < 1024) {
        int o = blockIdx.x * 256 + threadIdx.x;   // < Kn*64
        int kt = o >> 12, r1 = o & 4095;
        int ksub = r1 >> 10, r2 = r1 & 1023;
        int s = r2 >> 7, r3 = r2 & 127;
        int lane = r3 >> 2, r = r3 & 3;
        int g = lane >> 2, t = lane & 3;
        int row = kt * 64 + ksub * 16 + g + 8 * (r & 1);
        int q0  = s * 16 + 2 * t + 8 * (r >> 1);
        __half h0 = __float2half(emb[row * Qd + q0]);
        __half h1 = __float2half(emb[row * Qd + q0 + 1]);
        d_eA16[o] = (uint32_t)__half_as_ushort(h0) |
                    ((uint32_t)__half_as_ushort(h1) << 16);
    } else {
        int w = ((blockIdx.x - 1024) * 256 + threadIdx.x) >> 5;   // < Kn
        int lane = threadIdx.x & 31;
        const float* row = emb + (size_t)w * Qd;
        float s = 0.0f;
        #pragma unroll
        for (int j = 0; j < Qd / 32; ++j) {
            float v = row[lane + j * 32];
            s = fmaf(v, v, s);
        }
        #pragma unroll
        for (int off = 16; off > 0; off >>= 1)
            s += __shfl_down_sync(0xffffffffu, s, off);
        if (lane == 0) d_emb_sq[w] = s;
    }
}

// ---------------- main kernel -----------------------------------------------
__global__ void __launch_bounds__(THREADS, 1)
vq_main_kernel(const float* __restrict__ z, const float* __restrict__ W,
               const float* __restrict__ emb, float* __restrict__ out) {
    extern __shared__ float fbase[];
    const uint32_t smemA_u = smem_u32(fbase) + (uint32_t)P_A * 4u;

    const int tid  = threadIdx.x;
    const int wid  = tid >> 5;
    const int lane = tid & 31;
    const int b    = blockIdx.y;
    const int n0b  = blockIdx.x * TN;
    const int bid  = b * (Nn / TN) + blockIdx.x;
    float* zef = d_zef + (size_t)bid * 16384;   // [q][n] fp32 ze scratch

    // -------- prefetch A tiles 0 and 1 into bufs 0,1 (free during ph1) -----
    {
        #pragma unroll
        for (int tl = 0; tl < 2; ++tl) {
            const uint32_t* sA = d_eA16 + (size_t)tl * 8192;
            const uint32_t dst = smemA_u + (uint32_t)tl * 32768u;
            #pragma unroll
            for (int k = 0; k < 4; ++k) {
                int c = tid + k * 512;
                cp_async16(dst + (uint32_t)c * 16u, sA + c * 4);
            }
            cp_commit();
        }
    }

    // ================= Phase 1: ze = W @ z[b] tile (FFMA2) ==================
    {
        float* Wt = fbase;                 // [c][q] stride ZE_STR
        float* zt = fbase + CK * ZE_STR;   // [c][n] stride ZE_STR
        const int ty1 = tid >> 5;          // q rows ty1*8..+7
        const int tx1 = tid & 31;          // n cols tx1*4..+3

        unsigned long long acc1[4][4];
        #pragma unroll
        for (int i = 0; i < 4; ++i)
            #pragma unroll
            for (int j = 0; j < 4; ++j) acc1[i][j] = 0ull;

        for (int c0 = 0; c0 < CIN; c0 += CK) {
            for (int i = tid; i < CK * Qd; i += THREADS) {
                int c = i & (CK - 1);
                int q = i >> 5;
                Wt[c * ZE_STR + q] = W[q * CIN + c0 + c];
            }
            const float* zsrc = z + ((size_t)b * CIN + c0) * Nn + n0b;
            for (int i = tid; i < CK * TN; i += THREADS) {
                int r = i >> 7, nn = i & 127;
                zt[r * ZE_STR + nn] = zsrc[(size_t)r * Nn + nn];
            }
            __syncthreads();
            #pragma unroll 4
            for (int c = 0; c < CK; ++c) {
                const ulonglong2 ap0 =
                    *reinterpret_cast<const ulonglong2*>(Wt + c * ZE_STR + ty1 * 8);
                const ulonglong2 ap1 =
                    *reinterpret_cast<const ulonglong2*>(Wt + c * ZE_STR + ty1 * 8 + 4);
                const float4 bv =
                    *reinterpret_cast<const float4*>(zt + c * ZE_STR + tx1 * 4);
                const unsigned long long bd0 = dup2(bv.x), bd1 = dup2(bv.y);
                const unsigned long long bd2 = dup2(bv.z), bd3 = dup2(bv.w);
                fma2(acc1[0][0], ap0.x, bd0); fma2(acc1[0][1], ap0.x, bd1);
                fma2(acc1[0][2], ap0.x, bd2); fma2(acc1[0][3], ap0.x, bd3);
                fma2(acc1[1][0], ap0.y, bd0); fma2(acc1[1][1], ap0.y, bd1);
                fma2(acc1[1][2], ap0.y, bd2); fma2(acc1[1][3], ap0.y, bd3);
                fma2(acc1[2][0], ap1.x, bd0); fma2(acc1[2][1], ap1.x, bd1);
                fma2(acc1[2][2], ap1.x, bd2); fma2(acc1[2][3], ap1.x, bd3);
                fma2(acc1[3][0], ap1.y, bd0); fma2(acc1[3][1], ap1.y, bd1);
                fma2(acc1[3][2], ap1.y, bd2); fma2(acc1[3][3], ap1.y, bd3);
            }
            __syncthreads();   // Wt/zt dead after last iteration
        }
        // epilogue: gmem fp32 ze [q][n], fp16 ZB (swizzled) in smem, zsq
        // partials. ZB uint4 index for q-pair (q0 even):
        //   s=q0>>4, s2=s>>1, odd=s&1, d=(q0>>3)&1, t2=(q0&7)>>1
        //   idx4 = (n*16 + s2*4 + t2) ^ ((n&1)<<2); word = odd*2 + d
        uint32_t* zb32 = reinterpret_cast<uint32_t*>(fbase + P_ZB);
        float psum[4] = {0.f, 0.f, 0.f, 0.f};
        #pragma unroll
        for (int qp = 0; qp < 4; ++qp) {
            const int qb = ty1 * 8 + 2 * qp;          // even
            const int s  = qb >> 4;
            const int s2 = s >> 1;
            const int od = s & 1;
            const int d  = (qb >> 3) & 1;
            const int t2 = (qb & 7) >> 1;
            #pragma unroll
            for (int nn = 0; nn < 4; ++nn) {
                float vlo, vhi; unpack2(vlo, vhi, acc1[qp][nn]);
                const int n = tx1 * 4 + nn;
                zef[qb * 128 + n]       = vlo;
                zef[(qb + 1) * 128 + n] = vhi;
                psum[nn] = fmaf(vlo, vlo, psum[nn]);
                psum[nn] = fmaf(vhi, vhi, psum[nn]);
                const int idx4 = (n * 16 + s2 * 4 + t2) ^ ((n & 1) << 2);
                __half h0 = __float2half(vlo);
                __half h1 = __float2half(vhi);
                zb32[idx4 * 4 + od * 2 + d] =
                    (uint32_t)__half_as_ushort(h0) |
                    ((uint32_t)__half_as_ushort(h1) << 16);
            }
        }
        #pragma unroll
        for (int nn = 0; nn < 4; ++nn)
            fbase[ZSC + ty1 * 128 + tx1 * 4 + nn] = psum[nn];
    }
    __syncthreads();

    // zsq reduce: 16 partials per n
    if (tid < 128) {
        float s = 0.0f;
        #pragma unroll
        for (int j = 0; j < 16; ++j) s += fbase[ZSC + j * 128 + tid];
        fbase[ZSQ + tid] = s;
    }
    __syncthreads();

    // ================= Phase 2: single-term fp16 mma, 3-stage ==============
    const int kw = wid & 3;          // 16-row k-subtile within each 64 half
    const int nw = wid >> 2;         // n-group: cols nw*32 .. +31
    const int g  = lane >> 2;
    const int t  = lane & 3;

    float zsqr[8];
    #pragma unroll
    for (int nt = 0; nt < 4; ++nt)
        #pragma unroll
        for (int e = 0; e < 2; ++e)
            zsqr[nt * 2 + e] = fbase[ZSQ + nw * 32 + nt * 8 + 2 * t + e];

    float mv1[8], mv2[8];
    int   mi1[8], mi2[8];
    #pragma unroll
    for (int i = 0; i < 8; ++i) {
        mv1[i] = 3.402823466e38f; mv2[i] = 3.402823466e38f;
        mi1[i] = 0; mi2[i] = 0;
    }

    int nbase[4], nsw[4];
    #pragma unroll
    for (int nt = 0; nt < 4; ++nt) {
        const int n = nw * 32 + nt * 8 + g;
        nbase[nt] = n * 16 + t;
        nsw[nt]   = (n & 1) << 2;
    }
    const uint4* zb4 = reinterpret_cast<const uint4*>(fbase + P_ZB);

    int buf = 0;   // tl % 3
    for (int tl = 0; tl < NTILES; ++tl) {
        if (tl < NTILES - 1) cp_wait1(); else cp_wait0();
        __syncthreads();   // single sync per tile (3-stage, disjoint restage)

        const uint4* Abase = reinterpret_cast<const uint4*>(
            fbase + P_A + buf * 8192);
        const uint4* A0 = Abase + kw * 256 + lane;         // ksub kw (kb=0)
        const uint4* A1 = Abase + (kw + 4) * 256 + lane;   // ksub kw+4 (kb=1)

        float C0[4][4], C1[4][4];
        #pragma unroll
        for (int i = 0; i < 4; ++i)
            #pragma unroll
            for (int j = 0; j < 4; ++j) { C0[i][j] = 0.0f; C1[i][j] = 0.0f; }

        #pragma unroll
        for (int s2 = 0; s2 < 4; ++s2) {
            const uint4 a0e = A0[(2 * s2) * 32];
            const uint4 a0o = A0[(2 * s2 + 1) * 32];
            const uint4 a1e = A1[(2 * s2) * 32];
            const uint4 a1o = A1[(2 * s2 + 1) * 32];
            #pragma unroll
            for (int nt = 0; nt < 4; ++nt) {
                const uint4 w = zb4[(nbase[nt] + s2 * 4) ^ nsw[nt]];
                mma_f16(C0[nt], a0e, w.x, w.y);   // step s=2*s2
                mma_f16(C0[nt], a0o, w.z, w.w);   // step s=2*s2+1
                mma_f16(C1[nt], a1e, w.x, w.y);
                mma_f16(C1[nt], a1o, w.z, w.w);
            }
        }

        // restage tile tl+2 into buf (tl+2)%3 (disjoint from tl%3, (tl+1)%3)
        if (tl + 2 < NTILES) {
            int buf2 = buf + 2; if (buf2 >= 3) buf2 -= 3;
            const uint32_t* sA = d_eA16 + (size_t)(tl + 2) * 8192;
            const uint32_t dst = smemA_u + (uint32_t)buf2 * 32768u;
            #pragma unroll
            for (int k = 0; k < 4; ++k) {
                int c = tid + k * 512;
                cp_async16(dst + (uint32_t)c * 16u, sA + c * 4);
            }
            cp_commit();
        }

        // epilogue: d2, per-thread top-2 per column
        const int k0 = tl * KTile + kw * 16;        // kb=0
        const int k1 = k0 + 64;                     // kb=1
        const float e00 = __ldg(&d_emb_sq[k0 + g]);
        const float e08 = __ldg(&d_emb_sq[k0 + g + 8]);
        const float e10 = __ldg(&d_emb_sq[k1 + g]);
        const float e18 = __ldg(&d_emb_sq[k1 + g + 8]);
        #pragma unroll
        for (int nt = 0; nt < 4; ++nt)
            #pragma unroll
            for (int e = 0; e < 2; ++e) {
                const int i = nt * 2 + e;
                float d2; int k;
                #pragma unroll
                for (int c = 0; c < 4; ++c) {
                    switch (c) {
                        case 0: d2 = fmaf(-2.0f, C0[nt][e], zsqr[i]) + e00;
                                k = k0 + g; break;
                        case 1: d2 = fmaf(-2.0f, C0[nt][2 + e], zsqr[i]) + e08;
                                k = k0 + g + 8; break;
                        case 2: d2 = fmaf(-2.0f, C1[nt][e], zsqr[i]) + e10;
                                k = k1 + g; break;
                        default: d2 = fmaf(-2.0f, C1[nt][2 + e], zsqr[i]) + e18;
                                k = k1 + g + 8; break;
                    }
                    if (d2 < mv1[i]) {
                        mv2[i] = mv1[i]; mi2[i] = mi1[i];
                        mv1[i] = d2;     mi1[i] = k;
                    } else if (d2 < mv2[i]) {
                        mv2[i] = d2; mi2[i] = k;
                    }
                }
            }

        if (++buf == 3) buf = 0;
    }
    __syncthreads();

    // ====== cross-thread top-4 reduce + exact fp32 rescore per column ======
    {
        float* rv = fbase + P_A;                          // [64 slots][128 n]
        int*   ri = reinterpret_cast<int*>(fbase + P_A + 8192);
        const int slot2 = (kw * 8 + g) * 2;
        #pragma unroll
        for (int nt = 0; nt < 4; ++nt)
            #pragma unroll
            for (int e = 0; e < 2; ++e) {
                const int n = nw * 32 + nt * 8 + 2 * t + e;
                rv[slot2 * 128 + n]       = mv1[nt * 2 + e];
                ri[slot2 * 128 + n]       = mi1[nt * 2 + e];
                rv[(slot2 + 1) * 128 + n] = mv2[nt * 2 + e];
                ri[(slot2 + 1) * 128 + n] = mi2[nt * 2 + e];
            }
        __syncthreads();
        if (tid < 128) {
            float bv[4] = {3.402823466e38f, 3.402823466e38f,
                           3.402823466e38f, 3.402823466e38f};
            int   bi[4] = {0, 0, 0, 0};
            for (int sl = 0; sl < 64; ++sl) {
                const float v  = rv[sl * 128 + tid];
                const int   ix = ri[sl * 128 + tid];
                if (v < bv[3] || (v == bv[3] && ix < bi[3])) {
                    bv[3] = v; bi[3] = ix;
                    #pragma unroll
                    for (int j = 3; j > 0; --j) {
                        if (bv[j] < bv[j-1] ||
                            (bv[j] == bv[j-1] && bi[j] < bi[j-1])) {
                            float tv = bv[j]; bv[j] = bv[j-1]; bv[j-1] = tv;
                            int   ti = bi[j]; bi[j] = bi[j-1]; bi[j-1] = ti;
                        }
                    }
                }
            }
            // exact fp32 rescore of 4 candidates (ze from gmem/L2)
            const float* ep[4];
            #pragma unroll
            for (int c = 0; c < 4; ++c) ep[c] = emb + (size_t)bi[c] * Qd;
            float dot[4] = {0.f, 0.f, 0.f, 0.f};
            #pragma unroll 4
            for (int q = 0; q < Qd; ++q) {
                const float zv = zef[q * 128 + tid];
                #pragma unroll
                for (int c = 0; c < 4; ++c)
                    dot[c] = fmaf(ep[c][q], zv, dot[c]);
            }
            const float zsqn = fbase[ZSQ + tid];
            int   best = bi[0];
            float bd = fmaf(-2.0f, dot[0], zsqn) + __ldg(&d_emb_sq[bi[0]]);
            #pragma unroll
            for (int c = 1; c < 4; ++c) {
                const float dc =
                    fmaf(-2.0f, dot[c], zsqn) + __ldg(&d_emb_sq[bi[c]]);
                if (dc < bd || (dc == bd && bi[c] < best)) {
                    bd = dc; best = bi[c];
                }
            }
            reinterpret_cast<int*>(fbase + IDX)[tid] = best;
        }
        __syncthreads();
    }

    // ============== gather: out[b][q][n] = emb[idx[n]][q] ==================
    {
        const int* idx_s = reinterpret_cast<const int*>(fbase + IDX);
        float* gbuf = fbase + P_A;
        for (int i = tid; i < Qd * TN; i += THREADS) {
            int n = i >> 7, q = i & 127;
            gbuf[n * 128 + (q ^ (n & 31))] = emb[(size_t)idx_s[n] * Qd + q];
        }
        __syncthreads();
        for (int i = tid; i < Qd * TN; i += THREADS) {
            int q = i >> 7, n = i & 127;
            out[((size_t)b * Qd + q) * Nn + n0b + n] =
                gbuf[n * 128 + (q ^ (n & 31))];
        }
    }
}

// ---------------------------------------------------------------------------
extern "C" void kernel_launch(void* const* d_in, const int* in_sizes, int n_in,
                              void* d_out, int out_size) {
    const float* z = nullptr; const float* W = nullptr; const float* emb = nullptr;
    for (int i = 0; i < n_in; ++i) {
        if (in_sizes[i] == Bn * CIN * Nn)   z   = (const float*)d_in[i];
        else if (in_sizes[i] == Qd * CIN)   W   = (const float*)d_in[i];
        else if (in_sizes[i] == Kn * Qd)    emb = (const float*)d_in[i];
    }
    float* out = (float*)d_out;

    cudaFuncSetAttribute(vq_main_kernel,
                         cudaFuncAttributeMaxDynamicSharedMemorySize, SMEM_BYTES);

    prep_kernel<<<1536, 256>>>(emb);
    dim3 grid(Nn / TN, Bn);
    vq_main_kernel<<<grid, THREADS, SMEM_BYTES>>>(z, W, emb, out);
}

// round 15
// speedup vs baseline: 2.0117x; 1.0676x over previous
#include <cuda_runtime.h>
#include <cuda_fp16.h>
#include <cstdint>

// ---------------------------------------------------------------------------
// VQ_16243566313849 round 15: same per-column math as R13/R14 (fp16 single-
// term m16n8k16 phase-2, top-2/top-4 exact-fp32 rescore, FFMA2 phase-1), but
// restructured as 2 CTAs/SM x 256 threads (TN=64) so independent CTAs hide
// each other's barrier/cp_wait/latency stalls (profile: issue 33.7%, occ 25%,
// no pipe saturated -> latency-bound).
// ---------------------------------------------------------------------------

namespace {
constexpr int Bn  = 8;
constexpr int CIN = 768;
constexpr int Qd  = 128;
constexpr int Kn  = 4096;
constexpr int Nn  = 4096;

constexpr int TN      = 64;
constexpr int KTile   = 128;           // codebook rows per stage
constexpr int NTILES  = Kn / KTile;    // 32
constexpr int THREADS = 256;
constexpr int CK      = 32;            // phase-1 c chunk
constexpr int WT_STR  = 132;           // phase-1 Wt stride
constexpr int ZT_STR  = 68;            // phase-1 zt stride

// ---- smem word offsets ----
// Phase-1 Wt (32x132=4224) + zt (32x68=2176) live in [0, 6400); they are dead
// before ZB/ZSC are written in the epilogue.
constexpr int P_ZB = 0;                // fp16 B tiles: 64 rows x 64 words = 4096
constexpr int ZSQ  = 4096;             // 64 words
constexpr int IDX  = 4160;             // 64 words
constexpr int ZSC  = 4224;             // 16 x 64 = 1024 words (zsq partials)
constexpr int P_WT = 0;                // aliases ZB region (phase 1 only)
constexpr int P_ZT = 4224;             // zt at 4224 (aliases ZSC region, ph1)
constexpr int P_A  = 6400;             // 2 bufs x 8192 words (fp16 A tiles)
constexpr int SMEM_FLOATS = P_A + 2 * 8192;    // 22784
constexpr int SMEM_BYTES  = SMEM_FLOATS * 4;   // 91136 -> 2 CTAs/SM
}

__device__ float    d_emb_sq[Kn];
__device__ uint32_t d_eA16[(size_t)Kn * 64];         // frag-packed emb fp16x2
__device__ float    d_zef[(size_t)512 * 128 * 64];   // fp32 ze scratch [blk][q][n]

// ---------------- asm helpers ----------------------------------------------
__device__ __forceinline__ void fma2(unsigned long long& acc,
                                     unsigned long long a,
                                     unsigned long long b) {
    asm("fma.rn.f32x2 %0, %1, %2, %0;" : "+l"(acc) : "l"(a), "l"(b));
}
__device__ __forceinline__ unsigned long long dup2(float x) {
    unsigned long long r;
    unsigned int u = __float_as_uint(x);
    asm("mov.b64 %0, {%1, %1};" : "=l"(r) : "r"(u));
    return r;
}
__device__ __forceinline__ void unpack2(float& lo, float& hi,
                                        unsigned long long v) {
    unsigned int a, b2;
    asm("mov.b64 {%0, %1}, %2;" : "=r"(a), "=r"(b2) : "l"(v));
    lo = __uint_as_float(a); hi = __uint_as_float(b2);
}
__device__ __forceinline__ uint32_t smem_u32(const void* p) {
    uint32_t a;
    asm("{ .reg .u64 t; cvta.to.shared.u64 t, %1; cvt.u32.u64 %0, t; }"
        : "=r"(a) : "l"(p));
    return a;
}
__device__ __forceinline__ void cp_async16(uint32_t dst, const void* src) {
    asm volatile("cp.async.cg.shared.global [%0], [%1], 16;"
                 :: "r"(dst), "l"(src) : "memory");
}
__device__ __forceinline__ void cp_commit() {
    asm volatile("cp.async.commit_group;" ::: "memory");
}
__device__ __forceinline__ void cp_wait1() {
    asm volatile("cp.async.wait_group 1;" ::: "memory");
}
__device__ __forceinline__ void cp_wait0() {
    asm volatile("cp.async.wait_group 0;" ::: "memory");
}
__device__ __forceinline__ void mma_f16(float c[4], const uint4& a,
                                        uint32_t b0, uint32_t b1) {
    asm("mma.sync.aligned.m16n8k16.row.col.f32.f16.f16.f32 "
        "{%0,%1,%2,%3}, {%4,%5,%6,%7}, {%8,%9}, {%0,%1,%2,%3};"
        : "+f"(c[0]), "+f"(c[1]), "+f"(c[2]), "+f"(c[3])
        : "r"(a.x), "r"(a.y), "r"(a.z), "r"(a.w), "r"(b0), "r"(b1));
}

// ---------------- merged prologue kernel ------------------------------------
__global__ void prep_kernel(const float* __restrict__ emb) {
    if (blockIdx.x < 1024) {
        int o = blockIdx.x * 256 + threadIdx.x;   // < Kn*64
        int kt = o >> 12, r1 = o & 4095;
        int ksub = r1 >> 10, r2 = r1 & 1023;
        int s = r2 >> 7, r3 = r2 & 127;
        int lane = r3 >> 2, r = r3 & 3;
        int g = lane >> 2, t = lane & 3;
        int row = kt * 64 + ksub * 16 + g + 8 * (r & 1);
        int q0  = s * 16 + 2 * t + 8 * (r >> 1);
        __half h0 = __float2half(emb[row * Qd + q0]);
        __half h1 = __float2half(emb[row * Qd + q0 + 1]);
        d_eA16[o] = (uint32_t)__half_as_ushort(h0) |
                    ((uint32_t)__half_as_ushort(h1) << 16);
    } else {
        int w = ((blockIdx.x - 1024) * 256 + threadIdx.x) >> 5;   // < Kn
        int lane = threadIdx.x & 31;
        const float* row = emb + (size_t)w * Qd;
        float s = 0.0f;
        #pragma unroll
        for (int j = 0; j < Qd / 32; ++j) {
            float v = row[lane + j * 32];
            s = fmaf(v, v, s);
        }
        #pragma unroll
        for (int off = 16; off > 0; off >>= 1)
            s += __shfl_down_sync(0xffffffffu, s, off);
        if (lane == 0) d_emb_sq[w] = s;
    }
}

// ---------------- main kernel -----------------------------------------------
__global__ void __launch_bounds__(THREADS, 2)
vq_main_kernel(const float* __restrict__ z, const float* __restrict__ W,
               const float* __restrict__ emb, float* __restrict__ out) {
    extern __shared__ float fbase[];
    const uint32_t smemA_u = smem_u32(fbase) + (uint32_t)P_A * 4u;

    const int tid  = threadIdx.x;
    const int wid  = tid >> 5;
    const int lane = tid & 31;
    const int b    = blockIdx.y;
    const int n0b  = blockIdx.x * TN;
    const int bid  = b * (Nn / TN) + blockIdx.x;
    float* zef = d_zef + (size_t)bid * (Qd * TN);   // [q][n] fp32 ze scratch

    // -------- prefetch A tiles 0 and 1 (P_A free during phase 1) ----------
    {
        #pragma unroll
        for (int tl = 0; tl < 2; ++tl) {
            const uint32_t* sA = d_eA16 + (size_t)tl * 8192;
            const uint32_t dst = smemA_u + (uint32_t)tl * 32768u;
            #pragma unroll
            for (int k = 0; k < 8; ++k) {
                int c = tid + k * 256;
                cp_async16(dst + (uint32_t)c * 16u, sA + c * 4);
            }
            cp_commit();
        }
    }

    // ================= Phase 1: ze = W @ z[b] tile (FFMA2) ==================
    {
        float* Wt = fbase + P_WT;          // [c][q] stride WT_STR
        float* zt = fbase + P_ZT;          // [c][n] stride ZT_STR
        const int ty1 = tid >> 4;          // 0..15 -> q rows ty1*8..+7
        const int tx1 = tid & 15;          // 0..15 -> n cols tx1*4..+3

        unsigned long long acc1[4][4];
        #pragma unroll
        for (int i = 0; i < 4; ++i)
            #pragma unroll
            for (int j = 0; j < 4; ++j) acc1[i][j] = 0ull;

        for (int c0 = 0; c0 < CIN; c0 += CK) {
            for (int i = tid; i < CK * Qd; i += THREADS) {
                int c = i & (CK - 1);
                int q = i >> 5;
                Wt[c * WT_STR + q] = W[q * CIN + c0 + c];
            }
            const float* zsrc = z + ((size_t)b * CIN + c0) * Nn + n0b;
            for (int i = tid; i < CK * TN; i += THREADS) {
                int r = i >> 6, nn = i & 63;
                zt[r * ZT_STR + nn] = zsrc[(size_t)r * Nn + nn];
            }
            __syncthreads();
            #pragma unroll 4
            for (int c = 0; c < CK; ++c) {
                const ulonglong2 ap0 =
                    *reinterpret_cast<const ulonglong2*>(Wt + c * WT_STR + ty1 * 8);
                const ulonglong2 ap1 =
                    *reinterpret_cast<const ulonglong2*>(Wt + c * WT_STR + ty1 * 8 + 4);
                const float4 bv =
                    *reinterpret_cast<const float4*>(zt + c * ZT_STR + tx1 * 4);
                const unsigned long long bd0 = dup2(bv.x), bd1 = dup2(bv.y);
                const unsigned long long bd2 = dup2(bv.z), bd3 = dup2(bv.w);
                fma2(acc1[0][0], ap0.x, bd0); fma2(acc1[0][1], ap0.x, bd1);
                fma2(acc1[0][2], ap0.x, bd2); fma2(acc1[0][3], ap0.x, bd3);
                fma2(acc1[1][0], ap0.y, bd0); fma2(acc1[1][1], ap0.y, bd1);
                fma2(acc1[1][2], ap0.y, bd2); fma2(acc1[1][3], ap0.y, bd3);
                fma2(acc1[2][0], ap1.x, bd0); fma2(acc1[2][1], ap1.x, bd1);
                fma2(acc1[2][2], ap1.x, bd2); fma2(acc1[2][3], ap1.x, bd3);
                fma2(acc1[3][0], ap1.y, bd0); fma2(acc1[3][1], ap1.y, bd1);
                fma2(acc1[3][2], ap1.y, bd2); fma2(acc1[3][3], ap1.y, bd3);
            }
            __syncthreads();   // Wt/zt dead after last iteration
        }
        // epilogue: gmem fp32 ze [q][n], fp16 ZB (swizzled) in smem, zsq
        // partials. ZB uint4 index for q-pair (q0 even):
        //   s=q0>>4, s2=s>>1, odd=s&1, d=(q0>>3)&1, t2=(q0&7)>>1
        //   idx4 = (n*16 + s2*4 + t2) ^ ((n&1)<<2); word = odd*2 + d
        uint32_t* zb32 = reinterpret_cast<uint32_t*>(fbase + P_ZB);
        float psum[4] = {0.f, 0.f, 0.f, 0.f};
        #pragma unroll
        for (int qp = 0; qp < 4; ++qp) {
            const int qb = ty1 * 8 + 2 * qp;          // even
            const int s  = qb >> 4;
            const int s2 = s >> 1;
            const int od = s & 1;
            const int d  = (qb >> 3) & 1;
            const int t2 = (qb & 7) >> 1;
            #pragma unroll
            for (int nn = 0; nn < 4; ++nn) {
                float vlo, vhi; unpack2(vlo, vhi, acc1[qp][nn]);
                const int n = tx1 * 4 + nn;
                zef[qb * TN + n]       = vlo;
                zef[(qb + 1) * TN + n] = vhi;
                psum[nn] = fmaf(vlo, vlo, psum[nn]);
                psum[nn] = fmaf(vhi, vhi, psum[nn]);
                const int idx4 = (n * 16 + s2 * 4 + t2) ^ ((n & 1) << 2);
                __half h0 = __float2half(vlo);
                __half h1 = __float2half(vhi);
                zb32[idx4 * 4 + od * 2 + d] =
                    (uint32_t)__half_as_ushort(h0) |
                    ((uint32_t)__half_as_ushort(h1) << 16);
            }
        }
        #pragma unroll
        for (int nn = 0; nn < 4; ++nn)
            fbase[ZSC + ty1 * TN + tx1 * 4 + nn] = psum[nn];
    }
    __syncthreads();

    // zsq reduce: 16 partials per n
    if (tid < TN) {
        float s = 0.0f;
        #pragma unroll
        for (int j = 0; j < 16; ++j) s += fbase[ZSC + j * TN + tid];
        fbase[ZSQ + tid] = s;
    }
    __syncthreads();

    // ================= Phase 2: single-term fp16 mma =======================
    const int kw = wid & 3;          // 16-row k-subtile within each 64 half
    const int nw = wid >> 2;         // 0..1 -> n cols nw*32..+31
    const int g  = lane >> 2;
    const int t  = lane & 3;

    float zsqr[8];
    #pragma unroll
    for (int nt = 0; nt < 4; ++nt)
        #pragma unroll
        for (int e = 0; e < 2; ++e)
            zsqr[nt * 2 + e] = fbase[ZSQ + nw * 32 + nt * 8 + 2 * t + e];

    float mv1[8], mv2[8];
    int   mi1[8], mi2[8];
    #pragma unroll
    for (int i = 0; i < 8; ++i) {
        mv1[i] = 3.402823466e38f; mv2[i] = 3.402823466e38f;
        mi1[i] = 0; mi2[i] = 0;
    }

    int nbase[4], nsw[4];
    #pragma unroll
    for (int nt = 0; nt < 4; ++nt) {
        const int n = nw * 32 + nt * 8 + g;
        nbase[nt] = n * 16 + t;
        nsw[nt]   = (n & 1) << 2;
    }
    const uint4* zb4 = reinterpret_cast<const uint4*>(fbase + P_ZB);

    for (int tl = 0; tl < NTILES; ++tl) {
        if (tl < NTILES - 1) cp_wait1(); else cp_wait0();
        __syncthreads();

        const uint4* Abase = reinterpret_cast<const uint4*>(
            fbase + P_A + (tl & 1) * 8192);
        const uint4* A0 = Abase + kw * 256 + lane;         // ksub kw (kb=0)
        const uint4* A1 = Abase + (kw + 4) * 256 + lane;   // ksub kw+4 (kb=1)

        float C0[4][4], C1[4][4];
        #pragma unroll
        for (int i = 0; i < 4; ++i)
            #pragma unroll
            for (int j = 0; j < 4; ++j) { C0[i][j] = 0.0f; C1[i][j] = 0.0f; }

        #pragma unroll
        for (int s2 = 0; s2 < 4; ++s2) {
            const uint4 a0e = A0[(2 * s2) * 32];
            const uint4 a0o = A0[(2 * s2 + 1) * 32];
            const uint4 a1e = A1[(2 * s2) * 32];
            const uint4 a1o = A1[(2 * s2 + 1) * 32];
            #pragma unroll
            for (int nt = 0; nt < 4; ++nt) {
                const uint4 w = zb4[(nbase[nt] + s2 * 4) ^ nsw[nt]];
                mma_f16(C0[nt], a0e, w.x, w.y);   // step s=2*s2
                mma_f16(C0[nt], a0o, w.z, w.w);   // step s=2*s2+1
                mma_f16(C1[nt], a1e, w.x, w.y);
                mma_f16(C1[nt], a1o, w.z, w.w);
            }
        }

        // epilogue: d2, per-thread top-2 per column
        const int k0 = tl * KTile + kw * 16;        // kb=0
        const int k1 = k0 + 64;                     // kb=1
        const float e00 = __ldg(&d_emb_sq[k0 + g]);
        const float e08 = __ldg(&d_emb_sq[k0 + g + 8]);
        const float e10 = __ldg(&d_emb_sq[k1 + g]);
        const float e18 = __ldg(&d_emb_sq[k1 + g + 8]);
        #pragma unroll
        for (int nt = 0; nt < 4; ++nt)
            #pragma unroll
            for (int e = 0; e < 2; ++e) {
                const int i = nt * 2 + e;
                float d2; int k;
                #pragma unroll
                for (int c = 0; c < 4; ++c) {
                    switch (c) {
                        case 0: d2 = fmaf(-2.0f, C0[nt][e], zsqr[i]) + e00;
                                k = k0 + g; break;
                        case 1: d2 = fmaf(-2.0f, C0[nt][2 + e], zsqr[i]) + e08;
                                k = k0 + g + 8; break;
                        case 2: d2 = fmaf(-2.0f, C1[nt][e], zsqr[i]) + e10;
                                k = k1 + g; break;
                        default: d2 = fmaf(-2.0f, C1[nt][2 + e], zsqr[i]) + e18;
                                k = k1 + g + 8; break;
                    }
                    if (d2 < mv1[i]) {
                        mv2[i] = mv1[i]; mi2[i] = mi1[i];
                        mv1[i] = d2;     mi1[i] = k;
                    } else if (d2 < mv2[i]) {
                        mv2[i] = d2; mi2[i] = k;
                    }
                }
            }

        __syncthreads();   // all warps done with buffer (tl&1) before restage
        if (tl + 2 < NTILES) {
            const uint32_t* sA = d_eA16 + (size_t)(tl + 2) * 8192;
            const uint32_t dst = smemA_u + (uint32_t)(tl & 1) * 32768u;
            #pragma unroll
            for (int k = 0; k < 8; ++k) {
                int c = tid + k * 256;
                cp_async16(dst + (uint32_t)c * 16u, sA + c * 4);
            }
            cp_commit();
        }
    }
    __syncthreads();

    // ====== cross-thread top-4 reduce + exact fp32 rescore per column ======
    {
        float* rv = fbase + P_A;                          // [64 slots][64 n]
        int*   ri = reinterpret_cast<int*>(fbase + P_A + 4096);
        const int slot2 = (kw * 8 + g) * 2;
        #pragma unroll
        for (int nt = 0; nt < 4; ++nt)
            #pragma unroll
            for (int e = 0; e < 2; ++e) {
                const int n = nw * 32 + nt * 8 + 2 * t + e;
                rv[slot2 * TN + n]       = mv1[nt * 2 + e];
                ri[slot2 * TN + n]       = mi1[nt * 2 + e];
                rv[(slot2 + 1) * TN + n] = mv2[nt * 2 + e];
                ri[(slot2 + 1) * TN + n] = mi2[nt * 2 + e];
            }
        __syncthreads();
        if (tid < TN) {
            float bv[4] = {3.402823466e38f, 3.402823466e38f,
                           3.402823466e38f, 3.402823466e38f};
            int   bi[4] = {0, 0, 0, 0};
            for (int sl = 0; sl < 64; ++sl) {
                const float v  = rv[sl * TN + tid];
                const int   ix = ri[sl * TN + tid];
                if (v < bv[3] || (v == bv[3] && ix < bi[3])) {
                    bv[3] = v; bi[3] = ix;
                    #pragma unroll
                    for (int j = 3; j > 0; --j) {
                        if (bv[j] < bv[j-1] ||
                            (bv[j] == bv[j-1] && bi[j] < bi[j-1])) {
                            float tv = bv[j]; bv[j] = bv[j-1]; bv[j-1] = tv;
                            int   ti = bi[j]; bi[j] = bi[j-1]; bi[j-1] = ti;
                        }
                    }
                }
            }
            // exact fp32 rescore of 4 candidates (ze from gmem/L2)
            const float* ep[4];
            #pragma unroll
            for (int c = 0; c < 4; ++c) ep[c] = emb + (size_t)bi[c] * Qd;
            float dot[4] = {0.f, 0.f, 0.f, 0.f};
            #pragma unroll 4
            for (int q = 0; q < Qd; ++q) {
                const float zv = zef[q * TN + tid];
                #pragma unroll
                for (int c = 0; c < 4; ++c)
                    dot[c] = fmaf(ep[c][q], zv, dot[c]);
            }
            const float zsqn = fbase[ZSQ + tid];
            int   best = bi[0];
            float bd = fmaf(-2.0f, dot[0], zsqn) + __ldg(&d_emb_sq[bi[0]]);
            #pragma unroll
            for (int c = 1; c < 4; ++c) {
                const float dc =
                    fmaf(-2.0f, dot[c], zsqn) + __ldg(&d_emb_sq[bi[c]]);
                if (dc < bd || (dc == bd && bi[c] < best)) {
                    bd = dc; best = bi[c];
                }
            }
            reinterpret_cast<int*>(fbase + IDX)[tid] = best;
        }
        __syncthreads();
    }

    // ============== gather: out[b][q][n] = emb[idx[n]][q] ==================
    {
        const int* idx_s = reinterpret_cast<const int*>(fbase + IDX);
        float* gbuf = fbase + P_A;   // 64 x 128, XOR swizzle
        for (int i = tid; i < Qd * TN; i += THREADS) {
            int n = i >> 7, q = i & 127;
            gbuf[n * 128 + (q ^ (n & 31))] = emb[(size_t)idx_s[n] * Qd + q];
        }
        __syncthreads();
        for (int i = tid; i < Qd * TN; i += THREADS) {
            int q = i >> 6, n = i & 63;
            out[((size_t)b * Qd + q) * Nn + n0b + n] =
                gbuf[n * 128 + (q ^ (n & 31))];
        }
    }
}

// ---------------------------------------------------------------------------
extern "C" void kernel_launch(void* const* d_in, const int* in_sizes, int n_in,
                              void* d_out, int out_size) {
    const float* z = nullptr; const float* W = nullptr; const float* emb = nullptr;
    for (int i = 0; i < n_in; ++i) {
        if (in_sizes[i] == Bn * CIN * Nn)   z   = (const float*)d_in[i];
        else if (in_sizes[i] == Qd * CIN)   W   = (const float*)d_in[i];
        else if (in_sizes[i] == Kn * Qd)    emb = (const float*)d_in[i];
    }
    float* out = (float*)d_out;

    cudaFuncSetAttribute(vq_main_kernel,
                         cudaFuncAttributeMaxDynamicSharedMemorySize, SMEM_BYTES);

    prep_kernel<<<1536, 256>>>(emb);
    dim3 grid(Nn / TN, Bn);
    vq_main_kernel<<<grid, THREADS, SMEM_BYTES>>>(z, W, emb, out);
}

// round 16
// speedup vs baseline: 2.2096x; 1.0984x over previous
#include <cuda_runtime.h>
#include <cuda_fp16.h>
#include <cstdint>

// ---------------------------------------------------------------------------
// VQ_16243566313849 round 16: R15 structure (2 CTAs/SM x 256 thr, TN=64,
// fp16 single-term m16n8k16 phase-2, FFMA2 phase-1, exact-fp32 rescore) with
// the argmin state packed into uint32 keys:
//   key = (float_bits(d2) & ~0x7F) | ((tl<<2)|c)        (d2 > 0 always)
// -> mv/mi (32 regs) becomes p1/p2 (16 regs), top-2 update is 3 IMNMX.
// Theory: regs=128 cap was causing spills (issue 33.7%, L1 48%, instr count
// ~7x model); relieve pressure + cheaper epilogue.
// ---------------------------------------------------------------------------

namespace {
constexpr int Bn  = 8;
constexpr int CIN = 768;
constexpr int Qd  = 128;
constexpr int Kn  = 4096;
constexpr int Nn  = 4096;

constexpr int TN      = 64;
constexpr int KTile   = 128;           // codebook rows per stage
constexpr int NTILES  = Kn / KTile;    // 32
constexpr int THREADS = 256;
constexpr int CK      = 32;            // phase-1 c chunk
constexpr int WT_STR  = 132;           // phase-1 Wt stride
constexpr int ZT_STR  = 68;            // phase-1 zt stride

// ---- smem word offsets ----
constexpr int P_ZB = 0;                // fp16 B tiles: 4096 words
constexpr int ZSQ  = 4096;             // 64 words
constexpr int IDX  = 4160;             // 64 words
constexpr int ZSC  = 4224;             // 16 x 64 = 1024 words (zsq partials)
constexpr int P_WT = 0;                // aliases ZB region (phase 1 only)
constexpr int P_ZT = 4224;             // zt (aliases ZSC region, ph1)
constexpr int P_A  = 6400;             // 2 bufs x 8192 words (fp16 A tiles)
constexpr int SMEM_FLOATS = P_A + 2 * 8192;    // 22784
constexpr int SMEM_BYTES  = SMEM_FLOATS * 4;   // 91136 -> 2 CTAs/SM
}

__device__ float    d_emb_sq[Kn];
__device__ uint32_t d_eA16[(size_t)Kn * 64];         // frag-packed emb fp16x2
__device__ float    d_zef[(size_t)512 * 128 * 64];   // fp32 ze scratch [blk][q][n]

// ---------------- asm helpers ----------------------------------------------
__device__ __forceinline__ void fma2(unsigned long long& acc,
                                     unsigned long long a,
                                     unsigned long long b) {
    asm("fma.rn.f32x2 %0, %1, %2, %0;" : "+l"(acc) : "l"(a), "l"(b));
}
__device__ __forceinline__ unsigned long long dup2(float x) {
    unsigned long long r;
    unsigned int u = __float_as_uint(x);
    asm("mov.b64 %0, {%1, %1};" : "=l"(r) : "r"(u));
    return r;
}
__device__ __forceinline__ void unpack2(float& lo, float& hi,
                                        unsigned long long v) {
    unsigned int a, b2;
    asm("mov.b64 {%0, %1}, %2;" : "=r"(a), "=r"(b2) : "l"(v));
    lo = __uint_as_float(a); hi = __uint_as_float(b2);
}
__device__ __forceinline__ uint32_t smem_u32(const void* p) {
    uint32_t a;
    asm("{ .reg .u64 t; cvta.to.shared.u64 t, %1; cvt.u32.u64 %0, t; }"
        : "=r"(a) : "l"(p));
    return a;
}
__device__ __forceinline__ void cp_async16(uint32_t dst, const void* src) {
    asm volatile("cp.async.cg.shared.global [%0], [%1], 16;"
                 :: "r"(dst), "l"(src) : "memory");
}
__device__ __forceinline__ void cp_commit() {
    asm volatile("cp.async.commit_group;" ::: "memory");
}
__device__ __forceinline__ void cp_wait1() {
    asm volatile("cp.async.wait_group 1;" ::: "memory");
}
__device__ __forceinline__ void cp_wait0() {
    asm volatile("cp.async.wait_group 0;" ::: "memory");
}
__device__ __forceinline__ void mma_f16(float c[4], const uint4& a,
                                        uint32_t b0, uint32_t b1) {
    asm("mma.sync.aligned.m16n8k16.row.col.f32.f16.f16.f32 "
        "{%0,%1,%2,%3}, {%4,%5,%6,%7}, {%8,%9}, {%0,%1,%2,%3};"
        : "+f"(c[0]), "+f"(c[1]), "+f"(c[2]), "+f"(c[3])
        : "r"(a.x), "r"(a.y), "r"(a.z), "r"(a.w), "r"(b0), "r"(b1));
}
// top-2 packed-key update: 3 x IMNMX
__device__ __forceinline__ void top2_update(uint32_t& p1, uint32_t& p2,
                                            uint32_t key) {
    const uint32_t mx = (p1 > key) ? p1 : key;
    p1 = (p1 < key) ? p1 : key;
    p2 = (p2 < mx) ? p2 : mx;
}

// ---------------- merged prologue kernel ------------------------------------
__global__ void prep_kernel(const float* __restrict__ emb) {
    if (blockIdx.x < 1024) {
        int o = blockIdx.x * 256 + threadIdx.x;   // < Kn*64
        int kt = o >> 12, r1 = o & 4095;
        int ksub = r1 >> 10, r2 = r1 & 1023;
        int s = r2 >> 7, r3 = r2 & 127;
        int lane = r3 >> 2, r = r3 & 3;
        int g = lane >> 2, t = lane & 3;
        int row = kt * 64 + ksub * 16 + g + 8 * (r & 1);
        int q0  = s * 16 + 2 * t + 8 * (r >> 1);
        __half h0 = __float2half(emb[row * Qd + q0]);
        __half h1 = __float2half(emb[row * Qd + q0 + 1]);
        d_eA16[o] = (uint32_t)__half_as_ushort(h0) |
                    ((uint32_t)__half_as_ushort(h1) << 16);
    } else {
        int w = ((blockIdx.x - 1024) * 256 + threadIdx.x) >> 5;   // < Kn
        int lane = threadIdx.x & 31;
        const float* row = emb + (size_t)w * Qd;
        float s = 0.0f;
        #pragma unroll
        for (int j = 0; j < Qd / 32; ++j) {
            float v = row[lane + j * 32];
            s = fmaf(v, v, s);
        }
        #pragma unroll
        for (int off = 16; off > 0; off >>= 1)
            s += __shfl_down_sync(0xffffffffu, s, off);
        if (lane == 0) d_emb_sq[w] = s;
    }
}

// ---------------- main kernel -----------------------------------------------
__global__ void __launch_bounds__(THREADS, 2)
vq_main_kernel(const float* __restrict__ z, const float* __restrict__ W,
               const float* __restrict__ emb, float* __restrict__ out) {
    extern __shared__ float fbase[];
    const uint32_t smemA_u = smem_u32(fbase) + (uint32_t)P_A * 4u;

    const int tid  = threadIdx.x;
    const int wid  = tid >> 5;
    const int lane = tid & 31;
    const int b    = blockIdx.y;
    const int n0b  = blockIdx.x * TN;
    const int bid  = b * (Nn / TN) + blockIdx.x;
    float* zef = d_zef + (size_t)bid * (Qd * TN);   // [q][n] fp32 ze scratch

    // -------- prefetch A tiles 0 and 1 (P_A free during phase 1) ----------
    {
        #pragma unroll
        for (int tl = 0; tl < 2; ++tl) {
            const uint32_t* sA = d_eA16 + (size_t)tl * 8192;
            const uint32_t dst = smemA_u + (uint32_t)tl * 32768u;
            #pragma unroll
            for (int k = 0; k < 8; ++k) {
                int c = tid + k * 256;
                cp_async16(dst + (uint32_t)c * 16u, sA + c * 4);
            }
            cp_commit();
        }
    }

    // ================= Phase 1: ze = W @ z[b] tile (FFMA2) ==================
    {
        float* Wt = fbase + P_WT;          // [c][q] stride WT_STR
        float* zt = fbase + P_ZT;          // [c][n] stride ZT_STR
        const int ty1 = tid >> 4;          // 0..15 -> q rows ty1*8..+7
        const int tx1 = tid & 15;          // 0..15 -> n cols tx1*4..+3

        unsigned long long acc1[4][4];
        #pragma unroll
        for (int i = 0; i < 4; ++i)
            #pragma unroll
            for (int j = 0; j < 4; ++j) acc1[i][j] = 0ull;

        for (int c0 = 0; c0 < CIN; c0 += CK) {
            for (int i = tid; i < CK * Qd; i += THREADS) {
                int c = i & (CK - 1);
                int q = i >> 5;
                Wt[c * WT_STR + q] = W[q * CIN + c0 + c];
            }
            const float* zsrc = z + ((size_t)b * CIN + c0) * Nn + n0b;
            for (int i = tid; i < CK * TN; i += THREADS) {
                int r = i >> 6, nn = i & 63;
                zt[r * ZT_STR + nn] = zsrc[(size_t)r * Nn + nn];
            }
            __syncthreads();
            #pragma unroll 4
            for (int c = 0; c < CK; ++c) {
                const ulonglong2 ap0 =
                    *reinterpret_cast<const ulonglong2*>(Wt + c * WT_STR + ty1 * 8);
                const ulonglong2 ap1 =
                    *reinterpret_cast<const ulonglong2*>(Wt + c * WT_STR + ty1 * 8 + 4);
                const float4 bv =
                    *reinterpret_cast<const float4*>(zt + c * ZT_STR + tx1 * 4);
                const unsigned long long bd0 = dup2(bv.x), bd1 = dup2(bv.y);
                const unsigned long long bd2 = dup2(bv.z), bd3 = dup2(bv.w);
                fma2(acc1[0][0], ap0.x, bd0); fma2(acc1[0][1], ap0.x, bd1);
                fma2(acc1[0][2], ap0.x, bd2); fma2(acc1[0][3], ap0.x, bd3);
                fma2(acc1[1][0], ap0.y, bd0); fma2(acc1[1][1], ap0.y, bd1);
                fma2(acc1[1][2], ap0.y, bd2); fma2(acc1[1][3], ap0.y, bd3);
                fma2(acc1[2][0], ap1.x, bd0); fma2(acc1[2][1], ap1.x, bd1);
                fma2(acc1[2][2], ap1.x, bd2); fma2(acc1[2][3], ap1.x, bd3);
                fma2(acc1[3][0], ap1.y, bd0); fma2(acc1[3][1], ap1.y, bd1);
                fma2(acc1[3][2], ap1.y, bd2); fma2(acc1[3][3], ap1.y, bd3);
            }
            __syncthreads();   // Wt/zt dead after last iteration
        }
        // epilogue: gmem fp32 ze [q][n], fp16 ZB (swizzled) in smem, zsq
        // partials. ZB uint4 index for q-pair (q0 even):
        //   s=q0>>4, s2=s>>1, odd=s&1, d=(q0>>3)&1, t2=(q0&7)>>1
        //   idx4 = (n*16 + s2*4 + t2) ^ ((n&1)<<2); word = odd*2 + d
        uint32_t* zb32 = reinterpret_cast<uint32_t*>(fbase + P_ZB);
        float psum[4] = {0.f, 0.f, 0.f, 0.f};
        #pragma unroll
        for (int qp = 0; qp < 4; ++qp) {
            const int qb = ty1 * 8 + 2 * qp;          // even
            const int s  = qb >> 4;
            const int s2 = s >> 1;
            const int od = s & 1;
            const int d  = (qb >> 3) & 1;
            const int t2 = (qb & 7) >> 1;
            #pragma unroll
            for (int nn = 0; nn < 4; ++nn) {
                float vlo, vhi; unpack2(vlo, vhi, acc1[qp][nn]);
                const int n = tx1 * 4 + nn;
                zef[qb * TN + n]       = vlo;
                zef[(qb + 1) * TN + n] = vhi;
                psum[nn] = fmaf(vlo, vlo, psum[nn]);
                psum[nn] = fmaf(vhi, vhi, psum[nn]);
                const int idx4 = (n * 16 + s2 * 4 + t2) ^ ((n & 1) << 2);
                __half h0 = __float2half(vlo);
                __half h1 = __float2half(vhi);
                zb32[idx4 * 4 + od * 2 + d] =
                    (uint32_t)__half_as_ushort(h0) |
                    ((uint32_t)__half_as_ushort(h1) << 16);
            }
        }
        #pragma unroll
        for (int nn = 0; nn < 4; ++nn)
            fbase[ZSC + ty1 * TN + tx1 * 4 + nn] = psum[nn];
    }
    __syncthreads();

    // zsq reduce: 16 partials per n
    if (tid < TN) {
        float s = 0.0f;
        #pragma unroll
        for (int j = 0; j < 16; ++j) s += fbase[ZSC + j * TN + tid];
        fbase[ZSQ + tid] = s;
    }
    __syncthreads();

    // ================= Phase 2: single-term fp16 mma =======================
    const int kw = wid & 3;          // 16-row k-subtile within each 64 half
    const int nw = wid >> 2;         // 0..1 -> n cols nw*32..+31
    const int g  = lane >> 2;
    const int t  = lane & 3;

    float zsqr[8];
    #pragma unroll
    for (int nt = 0; nt < 4; ++nt)
        #pragma unroll
        for (int e = 0; e < 2; ++e)
            zsqr[nt * 2 + e] = fbase[ZSQ + nw * 32 + nt * 8 + 2 * t + e];

    // packed argmin keys: key = (bits(d2) & ~0x7F) | (tl<<2 | c)
    uint32_t p1[8], p2[8];
    #pragma unroll
    for (int i = 0; i < 8; ++i) { p1[i] = 0xFFFFFFFFu; p2[i] = 0xFFFFFFFFu; }

    int nbase[4], nsw[4];
    #pragma unroll
    for (int nt = 0; nt < 4; ++nt) {
        const int n = nw * 32 + nt * 8 + g;
        nbase[nt] = n * 16 + t;
        nsw[nt]   = (n & 1) << 2;
    }
    const uint4* zb4 = reinterpret_cast<const uint4*>(fbase + P_ZB);

    for (int tl = 0; tl < NTILES; ++tl) {
        if (tl < NTILES - 1) cp_wait1(); else cp_wait0();
        __syncthreads();

        const uint4* Abase = reinterpret_cast<const uint4*>(
            fbase + P_A + (tl & 1) * 8192);
        const uint4* A0 = Abase + kw * 256 + lane;         // ksub kw (kb=0)
        const uint4* A1 = Abase + (kw + 4) * 256 + lane;   // ksub kw+4 (kb=1)

        float C0[4][4], C1[4][4];
        #pragma unroll
        for (int i = 0; i < 4; ++i)
            #pragma unroll
            for (int j = 0; j < 4; ++j) { C0[i][j] = 0.0f; C1[i][j] = 0.0f; }

        #pragma unroll
        for (int s2 = 0; s2 < 4; ++s2) {
            const uint4 a0e = A0[(2 * s2) * 32];
            const uint4 a0o = A0[(2 * s2 + 1) * 32];
            const uint4 a1e = A1[(2 * s2) * 32];
            const uint4 a1o = A1[(2 * s2 + 1) * 32];
            #pragma unroll
            for (int nt = 0; nt < 4; ++nt) {
                const uint4 w = zb4[(nbase[nt] + s2 * 4) ^ nsw[nt]];
                mma_f16(C0[nt], a0e, w.x, w.y);   // step s=2*s2
                mma_f16(C0[nt], a0o, w.z, w.w);   // step s=2*s2+1
                mma_f16(C1[nt], a1e, w.x, w.y);
                mma_f16(C1[nt], a1o, w.z, w.w);
            }
        }

        // epilogue: packed-key top-2 per column
        const int code0 = tl << 2;
        const float e00 = __ldg(&d_emb_sq[tl * KTile + kw * 16 + g]);
        const float e08 = __ldg(&d_emb_sq[tl * KTile + kw * 16 + g + 8]);
        const float e10 = __ldg(&d_emb_sq[tl * KTile + kw * 16 + g + 64]);
        const float e18 = __ldg(&d_emb_sq[tl * KTile + kw * 16 + g + 72]);
        #pragma unroll
        for (int nt = 0; nt < 4; ++nt)
            #pragma unroll
            for (int e = 0; e < 2; ++e) {
                const int i = nt * 2 + e;
                float d2;
                d2 = fmaf(-2.0f, C0[nt][e], zsqr[i]) + e00;
                top2_update(p1[i], p2[i],
                    (__float_as_uint(d2) & 0xFFFFFF80u) | (code0 | 0));
                d2 = fmaf(-2.0f, C0[nt][2 + e], zsqr[i]) + e08;
                top2_update(p1[i], p2[i],
                    (__float_as_uint(d2) & 0xFFFFFF80u) | (code0 | 1));
                d2 = fmaf(-2.0f, C1[nt][e], zsqr[i]) + e10;
                top2_update(p1[i], p2[i],
                    (__float_as_uint(d2) & 0xFFFFFF80u) | (code0 | 2));
                d2 = fmaf(-2.0f, C1[nt][2 + e], zsqr[i]) + e18;
                top2_update(p1[i], p2[i],
                    (__float_as_uint(d2) & 0xFFFFFF80u) | (code0 | 3));
            }

        __syncthreads();   // all warps done with buffer (tl&1) before restage
        if (tl + 2 < NTILES) {
            const uint32_t* sA = d_eA16 + (size_t)(tl + 2) * 8192;
            const uint32_t dst = smemA_u + (uint32_t)(tl & 1) * 32768u;
            #pragma unroll
            for (int k = 0; k < 8; ++k) {
                int c = tid + k * 256;
                cp_async16(dst + (uint32_t)c * 16u, sA + c * 4);
            }
            cp_commit();
        }
    }
    __syncthreads();

    // ====== cross-thread top-4 reduce + exact fp32 rescore per column ======
    {
        uint32_t* rv = reinterpret_cast<uint32_t*>(fbase + P_A); // [64][TN]
        const int slot2 = (kw * 8 + g) * 2;
        #pragma unroll
        for (int nt = 0; nt < 4; ++nt)
            #pragma unroll
            for (int e = 0; e < 2; ++e) {
                const int n = nw * 32 + nt * 8 + 2 * t + e;
                rv[slot2 * TN + n]       = p1[nt * 2 + e];
                rv[(slot2 + 1) * TN + n] = p2[nt * 2 + e];
            }
        __syncthreads();
        if (tid < TN) {
            uint32_t kv[4] = {0xFFFFFFFFu, 0xFFFFFFFFu,
                              0xFFFFFFFFu, 0xFFFFFFFFu};
            int ks[4] = {0, 0, 0, 0};
            for (int sl = 0; sl < 64; ++sl) {
                const uint32_t v = rv[sl * TN + tid];
                if (v < kv[3]) {
                    kv[3] = v; ks[3] = sl;
                    #pragma unroll
                    for (int j = 3; j > 0; --j) {
                        if (kv[j] < kv[j-1]) {
                            uint32_t tv = kv[j]; kv[j] = kv[j-1]; kv[j-1] = tv;
                            int ti = ks[j]; ks[j] = ks[j-1]; ks[j-1] = ti;
                        }
                    }
                }
            }
            // decode candidates: slot -> (kw,g); code -> (tl,c)
            int bi[4];
            #pragma unroll
            for (int c = 0; c < 4; ++c) {
                const int kwg = ks[c] >> 1;
                const int kwd = kwg >> 3, gd = kwg & 7;
                const int code = (int)(kv[c] & 127u);
                const int tld = code >> 2, cc = code & 3;
                bi[c] = tld * KTile + kwd * 16 + gd +
                        8 * (cc & 1) + 64 * (cc >> 1);
            }
            // exact fp32 rescore of 4 candidates (ze from gmem/L2)
            const float* ep[4];
            #pragma unroll
            for (int c = 0; c < 4; ++c) ep[c] = emb + (size_t)bi[c] * Qd;
            float dot[4] = {0.f, 0.f, 0.f, 0.f};
            #pragma unroll 4
            for (int q = 0; q < Qd; ++q) {
                const float zv = zef[q * TN + tid];
                #pragma unroll
                for (int c = 0; c < 4; ++c)
                    dot[c] = fmaf(ep[c][q], zv, dot[c]);
            }
            const float zsqn = fbase[ZSQ + tid];
            int   best = bi[0];
            float bd = fmaf(-2.0f, dot[0], zsqn) + __ldg(&d_emb_sq[bi[0]]);
            #pragma unroll
            for (int c = 1; c < 4; ++c) {
                const float dc =
                    fmaf(-2.0f, dot[c], zsqn) + __ldg(&d_emb_sq[bi[c]]);
                if (dc < bd || (dc == bd && bi[c] < best)) {
                    bd = dc; best = bi[c];
                }
            }
            reinterpret_cast<int*>(fbase + IDX)[tid] = best;
        }
        __syncthreads();
    }

    // ============== gather: out[b][q][n] = emb[idx[n]][q] ==================
    {
        const int* idx_s = reinterpret_cast<const int*>(fbase + IDX);
        float* gbuf = fbase + P_A;   // 64 x 128, XOR swizzle
        for (int i = tid; i < Qd * TN; i += THREADS) {
            int n = i >> 7, q = i & 127;
            gbuf[n * 128 + (q ^ (n & 31))] = emb[(size_t)idx_s[n] * Qd + q];
        }
        __syncthreads();
        for (int i = tid; i < Qd * TN; i += THREADS) {
            int q = i >> 6, n = i & 63;
            out[((size_t)b * Qd + q) * Nn + n0b + n] =
                gbuf[n * 128 + (q ^ (n & 31))];
        }
    }
}

// ---------------------------------------------------------------------------
extern "C" void kernel_launch(void* const* d_in, const int* in_sizes, int n_in,
                              void* d_out, int out_size) {
    const float* z = nullptr; const float* W = nullptr; const float* emb = nullptr;
    for (int i = 0; i < n_in; ++i) {
        if (in_sizes[i] == Bn * CIN * Nn)   z   = (const float*)d_in[i];
        else if (in_sizes[i] == Qd * CIN)   W   = (const float*)d_in[i];
        else if (in_sizes[i] == Kn * Qd)    emb = (const float*)d_in[i];
    }
    float* out = (float*)d_out;

    cudaFuncSetAttribute(vq_main_kernel,
                         cudaFuncAttributeMaxDynamicSharedMemorySize, SMEM_BYTES);

    prep_kernel<<<1536, 256>>>(emb);
    dim3 grid(Nn / TN, Bn);
    vq_main_kernel<<<grid, THREADS, SMEM_BYTES>>>(z, W, emb, out);
}

// round 17
// speedup vs baseline: 2.2676x; 1.0262x over previous
#include <cuda_runtime.h>
#include <cuda_fp16.h>
#include <cstdint>

// ---------------------------------------------------------------------------
// VQ_16243566313849 round 17: R16 + fold d2 into the MMA:
//   - prep packs NEGATED emb fragments (A = -emb)
//   - accumulators init to esq2[k] = emb_sq[k]/2 + 16  (not 0)
//   -> C_final = esq2 - cross = argmin-equivalent score (zsq dropped: it is
//      constant per column). Epilogue = pack key + 3 IMNMX only.
// Top-2/thread + top-4 global + exact-fp32 rescore unchanged (proven).
// ---------------------------------------------------------------------------

namespace {
constexpr int Bn  = 8;
constexpr int CIN = 768;
constexpr int Qd  = 128;
constexpr int Kn  = 4096;
constexpr int Nn  = 4096;

constexpr int TN      = 64;
constexpr int KTile   = 128;           // codebook rows per stage
constexpr int NTILES  = Kn / KTile;    // 32
constexpr int THREADS = 256;
constexpr int CK      = 32;            // phase-1 c chunk
constexpr int WT_STR  = 132;           // phase-1 Wt stride
constexpr int ZT_STR  = 68;            // phase-1 zt stride

// ---- smem word offsets ----
constexpr int P_ZB = 0;                // fp16 B tiles: 4096 words
constexpr int ZSQ  = 4096;             // 64 words
constexpr int IDX  = 4160;             // 64 words
constexpr int ZSC  = 4224;             // 16 x 64 = 1024 words (zsq partials)
constexpr int P_WT = 0;                // aliases ZB region (phase 1 only)
constexpr int P_ZT = 4224;             // zt (aliases ZSC region, ph1)
constexpr int P_A  = 6400;             // 2 bufs x 8192 words (fp16 A tiles)
constexpr int SMEM_FLOATS = P_A + 2 * 8192;    // 22784
constexpr int SMEM_BYTES  = SMEM_FLOATS * 4;   // 91136 -> 2 CTAs/SM
}

__device__ float    d_emb_sq[Kn];                    // exact, for rescore
__device__ float    d_esq2[Kn];                      // emb_sq/2 + 16 (fast pass)
__device__ uint32_t d_eA16[(size_t)Kn * 64];         // frag-packed NEGATED emb
__device__ float    d_zef[(size_t)512 * 128 * 64];   // fp32 ze scratch [blk][q][n]

// ---------------- asm helpers ----------------------------------------------
__device__ __forceinline__ void fma2(unsigned long long& acc,
                                     unsigned long long a,
                                     unsigned long long b) {
    asm("fma.rn.f32x2 %0, %1, %2, %0;" : "+l"(acc) : "l"(a), "l"(b));
}
__device__ __forceinline__ unsigned long long dup2(float x) {
    unsigned long long r;
    unsigned int u = __float_as_uint(x);
    asm("mov.b64 %0, {%1, %1};" : "=l"(r) : "r"(u));
    return r;
}
__device__ __forceinline__ void unpack2(float& lo, float& hi,
                                        unsigned long long v) {
    unsigned int a, b2;
    asm("mov.b64 {%0, %1}, %2;" : "=r"(a), "=r"(b2) : "l"(v));
    lo = __uint_as_float(a); hi = __uint_as_float(b2);
}
__device__ __forceinline__ uint32_t smem_u32(const void* p) {
    uint32_t a;
    asm("{ .reg .u64 t; cvta.to.shared.u64 t, %1; cvt.u32.u64 %0, t; }"
        : "=r"(a) : "l"(p));
    return a;
}
__device__ __forceinline__ void cp_async16(uint32_t dst, const void* src) {
    asm volatile("cp.async.cg.shared.global [%0], [%1], 16;"
                 :: "r"(dst), "l"(src) : "memory");
}
__device__ __forceinline__ void cp_commit() {
    asm volatile("cp.async.commit_group;" ::: "memory");
}
__device__ __forceinline__ void cp_wait1() {
    asm volatile("cp.async.wait_group 1;" ::: "memory");
}
__device__ __forceinline__ void cp_wait0() {
    asm volatile("cp.async.wait_group 0;" ::: "memory");
}
__device__ __forceinline__ void mma_f16(float c[4], const uint4& a,
                                        uint32_t b0, uint32_t b1) {
    asm("mma.sync.aligned.m16n8k16.row.col.f32.f16.f16.f32 "
        "{%0,%1,%2,%3}, {%4,%5,%6,%7}, {%8,%9}, {%0,%1,%2,%3};"
        : "+f"(c[0]), "+f"(c[1]), "+f"(c[2]), "+f"(c[3])
        : "r"(a.x), "r"(a.y), "r"(a.z), "r"(a.w), "r"(b0), "r"(b1));
}
// top-2 packed-key update: 3 x IMNMX
__device__ __forceinline__ void top2_update(uint32_t& p1, uint32_t& p2,
                                            uint32_t key) {
    const uint32_t mx = (p1 > key) ? p1 : key;
    p1 = (p1 < key) ? p1 : key;
    p2 = (p2 < mx) ? p2 : mx;
}

// ---------------- merged prologue kernel ------------------------------------
__global__ void prep_kernel(const float* __restrict__ emb) {
    if (blockIdx.x < 1024) {
        int o = blockIdx.x * 256 + threadIdx.x;   // < Kn*64
        int kt = o >> 12, r1 = o & 4095;
        int ksub = r1 >> 10, r2 = r1 & 1023;
        int s = r2 >> 7, r3 = r2 & 127;
        int lane = r3 >> 2, r = r3 & 3;
        int g = lane >> 2, t = lane & 3;
        int row = kt * 64 + ksub * 16 + g + 8 * (r & 1);
        int q0  = s * 16 + 2 * t + 8 * (r >> 1);
        // NEGATED emb so the mma accumulates  esq2 - cross  directly
        __half h0 = __float2half(-emb[row * Qd + q0]);
        __half h1 = __float2half(-emb[row * Qd + q0 + 1]);
        d_eA16[o] = (uint32_t)__half_as_ushort(h0) |
                    ((uint32_t)__half_as_ushort(h1) << 16);
    } else {
        int w = ((blockIdx.x - 1024) * 256 + threadIdx.x) >> 5;   // < Kn
        int lane = threadIdx.x & 31;
        const float* row = emb + (size_t)w * Qd;
        float s = 0.0f;
        #pragma unroll
        for (int j = 0; j < Qd / 32; ++j) {
            float v = row[lane + j * 32];
            s = fmaf(v, v, s);
        }
        #pragma unroll
        for (int off = 16; off > 0; off >>= 1)
            s += __shfl_down_sync(0xffffffffu, s, off);
        if (lane == 0) {
            d_emb_sq[w] = s;
            d_esq2[w]   = 0.5f * s + 16.0f;
        }
    }
}

// ---------------- main kernel -----------------------------------------------
__global__ void __launch_bounds__(THREADS, 2)
vq_main_kernel(const float* __restrict__ z, const float* __restrict__ W,
               const float* __restrict__ emb, float* __restrict__ out) {
    extern __shared__ float fbase[];
    const uint32_t smemA_u = smem_u32(fbase) + (uint32_t)P_A * 4u;

    const int tid  = threadIdx.x;
    const int wid  = tid >> 5;
    const int lane = tid & 31;
    const int b    = blockIdx.y;
    const int n0b  = blockIdx.x * TN;
    const int bid  = b * (Nn / TN) + blockIdx.x;
    float* zef = d_zef + (size_t)bid * (Qd * TN);   // [q][n] fp32 ze scratch

    // -------- prefetch A tiles 0 and 1 (P_A free during phase 1) ----------
    {
        #pragma unroll
        for (int tl = 0; tl < 2; ++tl) {
            const uint32_t* sA = d_eA16 + (size_t)tl * 8192;
            const uint32_t dst = smemA_u + (uint32_t)tl * 32768u;
            #pragma unroll
            for (int k = 0; k < 8; ++k) {
                int c = tid + k * 256;
                cp_async16(dst + (uint32_t)c * 16u, sA + c * 4);
            }
            cp_commit();
        }
    }

    // ================= Phase 1: ze = W @ z[b] tile (FFMA2) ==================
    {
        float* Wt = fbase + P_WT;          // [c][q] stride WT_STR
        float* zt = fbase + P_ZT;          // [c][n] stride ZT_STR
        const int ty1 = tid >> 4;          // 0..15 -> q rows ty1*8..+7
        const int tx1 = tid & 15;          // 0..15 -> n cols tx1*4..+3

        unsigned long long acc1[4][4];
        #pragma unroll
        for (int i = 0; i < 4; ++i)
            #pragma unroll
            for (int j = 0; j < 4; ++j) acc1[i][j] = 0ull;

        for (int c0 = 0; c0 < CIN; c0 += CK) {
            for (int i = tid; i < CK * Qd; i += THREADS) {
                int c = i & (CK - 1);
                int q = i >> 5;
                Wt[c * WT_STR + q] = W[q * CIN + c0 + c];
            }
            const float* zsrc = z + ((size_t)b * CIN + c0) * Nn + n0b;
            for (int i = tid; i < CK * TN; i += THREADS) {
                int r = i >> 6, nn = i & 63;
                zt[r * ZT_STR + nn] = zsrc[(size_t)r * Nn + nn];
            }
            __syncthreads();
            #pragma unroll 4
            for (int c = 0; c < CK; ++c) {
                const ulonglong2 ap0 =
                    *reinterpret_cast<const ulonglong2*>(Wt + c * WT_STR + ty1 * 8);
                const ulonglong2 ap1 =
                    *reinterpret_cast<const ulonglong2*>(Wt + c * WT_STR + ty1 * 8 + 4);
                const float4 bv =
                    *reinterpret_cast<const float4*>(zt + c * ZT_STR + tx1 * 4);
                const unsigned long long bd0 = dup2(bv.x), bd1 = dup2(bv.y);
                const unsigned long long bd2 = dup2(bv.z), bd3 = dup2(bv.w);
                fma2(acc1[0][0], ap0.x, bd0); fma2(acc1[0][1], ap0.x, bd1);
                fma2(acc1[0][2], ap0.x, bd2); fma2(acc1[0][3], ap0.x, bd3);
                fma2(acc1[1][0], ap0.y, bd0); fma2(acc1[1][1], ap0.y, bd1);
                fma2(acc1[1][2], ap0.y, bd2); fma2(acc1[1][3], ap0.y, bd3);
                fma2(acc1[2][0], ap1.x, bd0); fma2(acc1[2][1], ap1.x, bd1);
                fma2(acc1[2][2], ap1.x, bd2); fma2(acc1[2][3], ap1.x, bd3);
                fma2(acc1[3][0], ap1.y, bd0); fma2(acc1[3][1], ap1.y, bd1);
                fma2(acc1[3][2], ap1.y, bd2); fma2(acc1[3][3], ap1.y, bd3);
            }
            __syncthreads();   // Wt/zt dead after last iteration
        }
        // epilogue: gmem fp32 ze [q][n], fp16 ZB (swizzled) in smem, zsq
        // partials. ZB uint4 index for q-pair (q0 even):
        //   s=q0>>4, s2=s>>1, odd=s&1, d=(q0>>3)&1, t2=(q0&7)>>1
        //   idx4 = (n*16 + s2*4 + t2) ^ ((n&1)<<2); word = odd*2 + d
        uint32_t* zb32 = reinterpret_cast<uint32_t*>(fbase + P_ZB);
        float psum[4] = {0.f, 0.f, 0.f, 0.f};
        #pragma unroll
        for (int qp = 0; qp < 4; ++qp) {
            const int qb = ty1 * 8 + 2 * qp;          // even
            const int s  = qb >> 4;
            const int s2 = s >> 1;
            const int od = s & 1;
            const int d  = (qb >> 3) & 1;
            const int t2 = (qb & 7) >> 1;
            #pragma unroll
            for (int nn = 0; nn < 4; ++nn) {
                float vlo, vhi; unpack2(vlo, vhi, acc1[qp][nn]);
                const int n = tx1 * 4 + nn;
                zef[qb * TN + n]       = vlo;
                zef[(qb + 1) * TN + n] = vhi;
                psum[nn] = fmaf(vlo, vlo, psum[nn]);
                psum[nn] = fmaf(vhi, vhi, psum[nn]);
                const int idx4 = (n * 16 + s2 * 4 + t2) ^ ((n & 1) << 2);
                __half h0 = __float2half(vlo);
                __half h1 = __float2half(vhi);
                zb32[idx4 * 4 + od * 2 + d] =
                    (uint32_t)__half_as_ushort(h0) |
                    ((uint32_t)__half_as_ushort(h1) << 16);
            }
        }
        #pragma unroll
        for (int nn = 0; nn < 4; ++nn)
            fbase[ZSC + ty1 * TN + tx1 * 4 + nn] = psum[nn];
    }
    __syncthreads();

    // zsq reduce: 16 partials per n (used only by the exact rescore)
    if (tid < TN) {
        float s = 0.0f;
        #pragma unroll
        for (int j = 0; j < 16; ++j) s += fbase[ZSC + j * TN + tid];
        fbase[ZSQ + tid] = s;
    }
    __syncthreads();

    // ================= Phase 2: single-term fp16 mma =======================
    const int kw = wid & 3;          // 16-row k-subtile within each 64 half
    const int nw = wid >> 2;         // 0..1 -> n cols nw*32..+31
    const int g  = lane >> 2;
    const int t  = lane & 3;

    // packed argmin keys: key = (bits(score) & ~0x7F) | (tl<<2 | c)
    uint32_t p1[8], p2[8];
    #pragma unroll
    for (int i = 0; i < 8; ++i) { p1[i] = 0xFFFFFFFFu; p2[i] = 0xFFFFFFFFu; }

    int nbase[4], nsw[4];
    #pragma unroll
    for (int nt = 0; nt < 4; ++nt) {
        const int n = nw * 32 + nt * 8 + g;
        nbase[nt] = n * 16 + t;
        nsw[nt]   = (n & 1) << 2;
    }
    const uint4* zb4 = reinterpret_cast<const uint4*>(fbase + P_ZB);

    for (int tl = 0; tl < NTILES; ++tl) {
        if (tl < NTILES - 1) cp_wait1(); else cp_wait0();
        __syncthreads();

        const uint4* Abase = reinterpret_cast<const uint4*>(
            fbase + P_A + (tl & 1) * 8192);
        const uint4* A0 = Abase + kw * 256 + lane;         // ksub kw (kb=0)
        const uint4* A1 = Abase + (kw + 4) * 256 + lane;   // ksub kw+4 (kb=1)

        // accumulators init to esq2[k]: C_final = esq2 - cross
        const int kbase = tl * KTile + kw * 16;
        const float e00 = __ldg(&d_esq2[kbase + g]);
        const float e08 = __ldg(&d_esq2[kbase + g + 8]);
        const float e10 = __ldg(&d_esq2[kbase + g + 64]);
        const float e18 = __ldg(&d_esq2[kbase + g + 72]);
        float C0[4][4], C1[4][4];
        #pragma unroll
        for (int nt = 0; nt < 4; ++nt) {
            C0[nt][0] = e00; C0[nt][1] = e00;
            C0[nt][2] = e08; C0[nt][3] = e08;
            C1[nt][0] = e10; C1[nt][1] = e10;
            C1[nt][2] = e18; C1[nt][3] = e18;
        }

        #pragma unroll
        for (int s2 = 0; s2 < 4; ++s2) {
            const uint4 a0e = A0[(2 * s2) * 32];
            const uint4 a0o = A0[(2 * s2 + 1) * 32];
            const uint4 a1e = A1[(2 * s2) * 32];
            const uint4 a1o = A1[(2 * s2 + 1) * 32];
            #pragma unroll
            for (int nt = 0; nt < 4; ++nt) {
                const uint4 w = zb4[(nbase[nt] + s2 * 4) ^ nsw[nt]];
                mma_f16(C0[nt], a0e, w.x, w.y);   // step s=2*s2
                mma_f16(C0[nt], a0o, w.z, w.w);   // step s=2*s2+1
                mma_f16(C1[nt], a1e, w.x, w.y);
                mma_f16(C1[nt], a1o, w.z, w.w);
            }
        }

        // epilogue: pack + top-2 only (score already = esq2 - cross)
        const int code0 = tl << 2;
        #pragma unroll
        for (int nt = 0; nt < 4; ++nt)
            #pragma unroll
            for (int e = 0; e < 2; ++e) {
                const int i = nt * 2 + e;
                top2_update(p1[i], p2[i],
                    (__float_as_uint(C0[nt][e]) & 0xFFFFFF80u) | (code0 | 0));
                top2_update(p1[i], p2[i],
                    (__float_as_uint(C0[nt][2 + e]) & 0xFFFFFF80u) | (code0 | 1));
                top2_update(p1[i], p2[i],
                    (__float_as_uint(C1[nt][e]) & 0xFFFFFF80u) | (code0 | 2));
                top2_update(p1[i], p2[i],
                    (__float_as_uint(C1[nt][2 + e]) & 0xFFFFFF80u) | (code0 | 3));
            }

        __syncthreads();   // all warps done with buffer (tl&1) before restage
        if (tl + 2 < NTILES) {
            const uint32_t* sA = d_eA16 + (size_t)(tl + 2) * 8192;
            const uint32_t dst = smemA_u + (uint32_t)(tl & 1) * 32768u;
            #pragma unroll
            for (int k = 0; k < 8; ++k) {
                int c = tid + k * 256;
                cp_async16(dst + (uint32_t)c * 16u, sA + c * 4);
            }
            cp_commit();
        }
    }
    __syncthreads();

    // ====== cross-thread top-4 reduce + exact fp32 rescore per column ======
    {
        uint32_t* rv = reinterpret_cast<uint32_t*>(fbase + P_A); // [64][TN]
        const int slot2 = (kw * 8 + g) * 2;
        #pragma unroll
        for (int nt = 0; nt < 4; ++nt)
            #pragma unroll
            for (int e = 0; e < 2; ++e) {
                const int n = nw * 32 + nt * 8 + 2 * t + e;
                rv[slot2 * TN + n]       = p1[nt * 2 + e];
                rv[(slot2 + 1) * TN + n] = p2[nt * 2 + e];
            }
        __syncthreads();
        if (tid < TN) {
            uint32_t kv[4] = {0xFFFFFFFFu, 0xFFFFFFFFu,
                              0xFFFFFFFFu, 0xFFFFFFFFu};
            int ks[4] = {0, 0, 0, 0};
            for (int sl = 0; sl < 64; ++sl) {
                const uint32_t v = rv[sl * TN + tid];
                if (v < kv[3]) {
                    kv[3] = v; ks[3] = sl;
                    #pragma unroll
                    for (int j = 3; j > 0; --j) {
                        if (kv[j] < kv[j-1]) {
                            uint32_t tv = kv[j]; kv[j] = kv[j-1]; kv[j-1] = tv;
                            int ti = ks[j]; ks[j] = ks[j-1]; ks[j-1] = ti;
                        }
                    }
                }
            }
            // decode candidates: slot -> (kw,g); code -> (tl,c)
            int bi[4];
            #pragma unroll
            for (int c = 0; c < 4; ++c) {
                const int kwg = ks[c] >> 1;
                const int kwd = kwg >> 3, gd = kwg & 7;
                const int code = (int)(kv[c] & 127u);
                const int tld = code >> 2, cc = code & 3;
                bi[c] = tld * KTile + kwd * 16 + gd +
                        8 * (cc & 1) + 64 * (cc >> 1);
            }
            // exact fp32 rescore of 4 candidates (ze from gmem/L2)
            const float* ep[4];
            #pragma unroll
            for (int c = 0; c < 4; ++c) ep[c] = emb + (size_t)bi[c] * Qd;
            float dot[4] = {0.f, 0.f, 0.f, 0.f};
            #pragma unroll 4
            for (int q = 0; q < Qd; ++q) {
                const float zv = zef[q * TN + tid];
                #pragma unroll
                for (int c = 0; c < 4; ++c)
                    dot[c] = fmaf(ep[c][q], zv, dot[c]);
            }
            const float zsqn = fbase[ZSQ + tid];
            int   best = bi[0];
            float bd = fmaf(-2.0f, dot[0], zsqn) + __ldg(&d_emb_sq[bi[0]]);
            #pragma unroll
            for (int c = 1; c < 4; ++c) {
                const float dc =
                    fmaf(-2.0f, dot[c], zsqn) + __ldg(&d_emb_sq[bi[c]]);
                if (dc < bd || (dc == bd && bi[c] < best)) {
                    bd = dc; best = bi[c];
                }
            }
            reinterpret_cast<int*>(fbase + IDX)[tid] = best;
        }
        __syncthreads();
    }

    // ============== gather: out[b][q][n] = emb[idx[n]][q] ==================
    {
        const int* idx_s = reinterpret_cast<const int*>(fbase + IDX);
        float* gbuf = fbase + P_A;   // 64 x 128, XOR swizzle
        for (int i = tid; i < Qd * TN; i += THREADS) {
            int n = i >> 7, q = i & 127;
            gbuf[n * 128 + (q ^ (n & 31))] = emb[(size_t)idx_s[n] * Qd + q];
        }
        __syncthreads();
        for (int i = tid; i < Qd * TN; i += THREADS) {
            int q = i >> 6, n = i & 63;
            out[((size_t)b * Qd + q) * Nn + n0b + n] =
                gbuf[n * 128 + (q ^ (n & 31))];
        }
    }
}

// ---------------------------------------------------------------------------
extern "C" void kernel_launch(void* const* d_in, const int* in_sizes, int n_in,
                              void* d_out, int out_size) {
    const float* z = nullptr; const float* W = nullptr; const float* emb = nullptr;
    for (int i = 0; i < n_in; ++i) {
        if (in_sizes[i] == Bn * CIN * Nn)   z   = (const float*)d_in[i];
        else if (in_sizes[i] == Qd * CIN)   W   = (const float*)d_in[i];
        else if (in_sizes[i] == Kn * Qd)    emb = (const float*)d_in[i];
    }
    float* out = (float*)d_out;

    cudaFuncSetAttribute(vq_main_kernel,
                         cudaFuncAttributeMaxDynamicSharedMemorySize, SMEM_BYTES);

    prep_kernel<<<1536, 256>>>(emb);
    dim3 grid(Nn / TN, Bn);
    vq_main_kernel<<<grid, THREADS, SMEM_BYTES>>>(z, W, emb, out);
}